// round 10
// baseline (speedup 1.0000x reference)
#include <cuda_runtime.h>
#include <cuda_bf16.h>
#include <math.h>
#include <stdint.h>

#define NB      8
#define SEQ     1024
#define DIM     512
#define NHEADS  8
#define DHEAD   64
#define INNER   512
#define M_TOT   (NB*SEQ)        /* 8192 */
#define BH      (NB*NHEADS)     /* 64 */

// ---- scratch (allocation-free: __device__ globals) ----
__device__ __nv_bfloat16 g_xhi [(size_t)M_TOT*DIM];     // pre-split x
__device__ __nv_bfloat16 g_xlo [(size_t)M_TOT*DIM];
__device__ __nv_bfloat16 g_aohi[(size_t)M_TOT*INNER];   // attn out, split
__device__ __nv_bfloat16 g_aolo[(size_t)M_TOT*INNER];
// pre-split bf16 q/k/v, [bh][n][d]; q has exp(temperature)*log2(e) folded in
__device__ __nv_bfloat16 g_qhi[(size_t)BH*SEQ*DHEAD];
__device__ __nv_bfloat16 g_qlo[(size_t)BH*SEQ*DHEAD];
__device__ __nv_bfloat16 g_khi[(size_t)BH*SEQ*DHEAD];
__device__ __nv_bfloat16 g_klo[(size_t)BH*SEQ*DHEAD];
__device__ __nv_bfloat16 g_vhi[(size_t)BH*SEQ*DHEAD];
__device__ __nv_bfloat16 g_vlo[(size_t)BH*SEQ*DHEAD];
// pre-transposed + split weights: [n][k] bf16
__device__ __nv_bfloat16 g_wqkv_hi[(size_t)3*INNER*DIM];
__device__ __nv_bfloat16 g_wqkv_lo[(size_t)3*INNER*DIM];
__device__ __nv_bfloat16 g_wout_hi[(size_t)DIM*INNER];
__device__ __nv_bfloat16 g_wout_lo[(size_t)DIM*INNER];

// ========================== helpers ===========================
__device__ __forceinline__ uint32_t smem_u32(const void* p) {
    uint32_t a;
    asm("{ .reg .u64 t; cvta.to.shared.u64 t, %1; cvt.u32.u64 %0, t; }" : "=r"(a) : "l"(p));
    return a;
}
__device__ __forceinline__ void ldm_x4(uint32_t* f, uint32_t addr) {
    asm volatile("ldmatrix.sync.aligned.m8n8.x4.shared.b16 {%0,%1,%2,%3}, [%4];"
                 : "=r"(f[0]), "=r"(f[1]), "=r"(f[2]), "=r"(f[3]) : "r"(addr));
}
__device__ __forceinline__ void ldm_x4t(uint32_t* f, uint32_t addr) {
    asm volatile("ldmatrix.sync.aligned.m8n8.x4.trans.shared.b16 {%0,%1,%2,%3}, [%4];"
                 : "=r"(f[0]), "=r"(f[1]), "=r"(f[2]), "=r"(f[3]) : "r"(addr));
}
__device__ __forceinline__ void mma_bf16(float* d, const uint32_t* a, const uint32_t* b) {
    asm("mma.sync.aligned.m16n8k16.row.col.f32.bf16.bf16.f32 "
        "{%0,%1,%2,%3}, {%4,%5,%6,%7}, {%8,%9}, {%0,%1,%2,%3};"
        : "+f"(d[0]), "+f"(d[1]), "+f"(d[2]), "+f"(d[3])
        : "r"(a[0]), "r"(a[1]), "r"(a[2]), "r"(a[3]), "r"(b[0]), "r"(b[1]));
}
__device__ __forceinline__ uint32_t pack_hi(float x, float y) {
    __nv_bfloat162 h = {__float2bfloat16(x), __float2bfloat16(y)};
    return *(uint32_t*)&h;
}
__device__ __forceinline__ uint32_t pack_lo(float x, float y) {
    float rx = x - __bfloat162float(__float2bfloat16(x));
    float ry = y - __bfloat162float(__float2bfloat16(y));
    __nv_bfloat162 l = {__float2bfloat16(rx), __float2bfloat16(ry)};
    return *(uint32_t*)&l;
}
// hardware EX2 (MUFU), independent of fast-math flags; ex2(-inf)=0
__device__ __forceinline__ float ex2(float x) {
    float y;
    asm("ex2.approx.f32 %0, %1;" : "=f"(y) : "f"(x));
    return y;
}
__device__ __forceinline__ void cp16(uint32_t sdst, const void* gsrc) {
    asm volatile("cp.async.cg.shared.global [%0], [%1], 16;" :: "r"(sdst), "l"(gsrc));
}
__device__ __forceinline__ void cp_commit() { asm volatile("cp.async.commit_group;"); }
template <int N> __device__ __forceinline__ void cp_wait() {
    asm volatile("cp.async.wait_group %0;" :: "n"(N));
}

// ============================================================================
// Prep kernels (unchanged)
// ============================================================================
__global__ __launch_bounds__(256) void xsplit_kernel(const float* __restrict__ X)
{
    size_t i = ((size_t)blockIdx.x * 256 + threadIdx.x) * 4;
    float4 v = *(const float4*)&X[i];
    *(uint2*)&g_xhi[i] = make_uint2(pack_hi(v.x, v.y), pack_hi(v.z, v.w));
    *(uint2*)&g_xlo[i] = make_uint2(pack_lo(v.x, v.y), pack_lo(v.z, v.w));
}

__global__ void wsplit_kernel(const float* __restrict__ W,
                              __nv_bfloat16* __restrict__ hi,
                              __nv_bfloat16* __restrict__ lo, int N)
{
    __shared__ float t[32][33];
    int n = blockIdx.x * 32 + threadIdx.x;
    int k = blockIdx.y * 32 + threadIdx.y;
    t[threadIdx.y][threadIdx.x] = W[(size_t)k * N + n];
    __syncthreads();
    int n2 = blockIdx.x * 32 + threadIdx.y;
    int k2 = blockIdx.y * 32 + threadIdx.x;
    float v = t[threadIdx.x][threadIdx.y];
    __nv_bfloat16 h = __float2bfloat16(v);
    hi[(size_t)n2 * DIM + k2] = h;
    lo[(size_t)n2 * DIM + k2] = __float2bfloat16(v - __bfloat162float(h));
}

// ============================================================================
// HMMA GEMM v2: 4 warps (2x2), warp tile 64x64, CTA tile 128x128, BK=32.
// smem reads per MAC halved vs v1 (0.042 B/MAC) -> smem port no longer binds.
// 2-stage cp.async pipeline. Split-bf16 3-MMA (hh/hl/lh sweeps).
// ============================================================================
#define BK   32
#define PAD  40
#define GST  10240
#define GSTAGE (4*GST)

__global__ __launch_bounds__(128, 2) void gemm_hmma_kernel(
    const __nv_bfloat16* __restrict__ Ahi,
    const __nv_bfloat16* __restrict__ Alo,
    const __nv_bfloat16* __restrict__ Bhi,
    const __nv_bfloat16* __restrict__ Blo,
    float* __restrict__ C, const float* __restrict__ temp, int mode)
{
    extern __shared__ char smem[];
    const uint32_t uS = smem_u32(smem);

    const int tx   = threadIdx.x;
    const int lane = tx & 31;
    const int wid  = tx >> 5;          // 0..3
    const int wm   = wid >> 1;         // 0..1 -> 64 rows
    const int wn   = wid & 1;          // 0..1 -> 64 cols
    const int row0 = blockIdx.y * 128;
    const int col0 = blockIdx.x * 128;

    // copy: thread tx owns row tx of each 128x32 buffer (4 x 16B chunks)
    auto issue = [&](int kc, int s) {
        uint32_t sb = uS + s * GSTAGE;
        size_t  ga = (size_t)(row0 + tx) * DIM + kc;
        size_t  gb = (size_t)(col0 + tx) * DIM + kc;
        uint32_t so = (uint32_t)(tx * PAD) * 2;
#pragma unroll
        for (int t = 0; t < 4; t++) {
            uint32_t o = so + t * 16;
            cp16(sb + o,           Ahi + ga + t * 8);
            cp16(sb + GST   + o,   Alo + ga + t * 8);
            cp16(sb + 2*GST + o,   Bhi + gb + t * 8);
            cp16(sb + 3*GST + o,   Blo + gb + t * 8);
        }
        cp_commit();
    };

    float acc[4][8][4];
#pragma unroll
    for (int i = 0; i < 4; i++)
#pragma unroll
        for (int j = 0; j < 8; j++)
#pragma unroll
            for (int t = 0; t < 4; t++) acc[i][j][t] = 0.f;

    const int a_row  = lane & 15;
    const int a_half = lane >> 4;
    const int b_row  = (lane & 7) + ((lane >> 4) << 3);
    const int b_half = (lane >> 3) & 1;

    issue(0, 0);
    const int KITER = DIM / BK;        // 16
    for (int kc = 0; kc < KITER; kc++) {
        if (kc + 1 < KITER) { issue((kc + 1) * BK, (kc + 1) & 1); cp_wait<1>(); }
        else                { cp_wait<0>(); }
        __syncthreads();

        const uint32_t sb = uS + (kc & 1) * GSTAGE;
        const uint32_t uAhi = sb, uAlo = sb + GST, uBhi = sb + 2*GST, uBlo = sb + 3*GST;
#pragma unroll
        for (int kk = 0; kk < 2; kk++) {
            uint32_t afh[4][4], afl[4][4];
#pragma unroll
            for (int mf = 0; mf < 4; mf++) {
                uint32_t boff = (uint32_t)((wm * 64 + mf * 16 + a_row) * PAD + kk * 16) * 2
                              + a_half * 16;
                ldm_x4(afh[mf], uAhi + boff);
                ldm_x4(afl[mf], uAlo + boff);
            }
            uint32_t bfh[8][2], bfl[8][2];
#pragma unroll
            for (int nf2 = 0; nf2 < 4; nf2++) {
                uint32_t boff = (uint32_t)((wn * 64 + nf2 * 16 + b_row) * PAD + kk * 16) * 2
                              + b_half * 16;
                uint32_t th[4], tl[4];
                ldm_x4(th, uBhi + boff);
                ldm_x4(tl, uBlo + boff);
                bfh[nf2*2][0] = th[0]; bfh[nf2*2][1] = th[1];
                bfh[nf2*2+1][0] = th[2]; bfh[nf2*2+1][1] = th[3];
                bfl[nf2*2][0] = tl[0]; bfl[nf2*2][1] = tl[1];
                bfl[nf2*2+1][0] = tl[2]; bfl[nf2*2+1][1] = tl[3];
            }
#pragma unroll
            for (int mf = 0; mf < 4; mf++)
#pragma unroll
                for (int nf = 0; nf < 8; nf++)
                    mma_bf16(acc[mf][nf], afh[mf], bfh[nf]);
#pragma unroll
            for (int mf = 0; mf < 4; mf++)
#pragma unroll
                for (int nf = 0; nf < 8; nf++)
                    mma_bf16(acc[mf][nf], afh[mf], bfl[nf]);
#pragma unroll
            for (int mf = 0; mf < 4; mf++)
#pragma unroll
                for (int nf = 0; nf < 8; nf++)
                    mma_bf16(acc[mf][nf], afl[mf], bfh[nf]);
        }
        __syncthreads();
    }

    const float sc = (mode == 0) ? __expf(*temp) * 1.44269504f : 1.f;
#pragma unroll
    for (int mf = 0; mf < 4; mf++) {
        int m_base = row0 + wm * 64 + mf * 16 + (lane >> 2);
#pragma unroll
        for (int nf = 0; nf < 8; nf++) {
            int c = col0 + wn * 64 + nf * 8 + 2 * (lane & 3);
            float2 v0 = make_float2(acc[mf][nf][0], acc[mf][nf][1]);
            float2 v1 = make_float2(acc[mf][nf][2], acc[mf][nf][3]);
            if (mode == 1) {
                *(float2*)&C[(size_t)m_base * DIM + c]       = v0;
                *(float2*)&C[(size_t)(m_base + 8) * DIM + c] = v1;
            } else {
                int which = c >> 9;
                int inner = c & 511;
                int h     = inner >> 6;
                int d     = inner & 63;
                __nv_bfloat16 *bh_, *bl_;
                if (which == 0) {
                    v0.x *= sc; v0.y *= sc; v1.x *= sc; v1.y *= sc;
                    bh_ = g_qhi; bl_ = g_qlo;
                } else if (which == 1) { bh_ = g_khi; bl_ = g_klo; }
                else                   { bh_ = g_vhi; bl_ = g_vlo; }
                int b0 = m_base >> 10, n0 = m_base & 1023;
                size_t off0 = ((size_t)((b0 * NHEADS + h) * SEQ + n0)) * DHEAD + d;
                *(uint32_t*)&bh_[off0] = pack_hi(v0.x, v0.y);
                *(uint32_t*)&bl_[off0] = pack_lo(v0.x, v0.y);
                int m1 = m_base + 8;
                int b1 = m1 >> 10, n1 = m1 & 1023;
                size_t off1 = ((size_t)((b1 * NHEADS + h) * SEQ + n1)) * DHEAD + d;
                *(uint32_t*)&bh_[off1] = pack_hi(v1.x, v1.y);
                *(uint32_t*)&bl_[off1] = pack_lo(v1.x, v1.y);
            }
        }
    }
}

// ============================================================================
// Flash attention (R9 shape): q-block 128, 4 warps x 32 q-rows, K-tiles 64.
// exp2 via explicit MUFU EX2. 2-stage cp.async, split-bf16 3-MMA.
// ============================================================================
#define KST   72
#define ABUF  9216
#define ASTAGE (4*ABUF)

__global__ __launch_bounds__(128, 2) void attn_hmma_kernel()
{
    extern __shared__ char smem[];
    const uint32_t uS = smem_u32(smem);

    const int tx   = threadIdx.x;
    const int lane = tx & 31;
    const int wq   = tx >> 5;
    const int bh   = blockIdx.y;
    const int q0   = blockIdx.x * 128;
    const size_t base = (size_t)bh * SEQ * DHEAD;

#pragma unroll
    for (int t = 0; t < 8; t++) {
        int id = tx + t * 128;
        int r  = id >> 3, c8 = (id & 7) << 3;
        uint32_t hb = (r < 64) ? 0u : (uint32_t)ABUF;
        uint32_t so = (uint32_t)((r & 63) * KST + c8) * 2;
        *(uint4*)(smem + hb + so)          = *(const uint4*)&g_qhi[base + (size_t)(q0 + r) * DHEAD + c8];
        *(uint4*)(smem + 2*ABUF + hb + so) = *(const uint4*)&g_qlo[base + (size_t)(q0 + r) * DHEAD + c8];
    }
    __syncthreads();

    const int a_row  = lane & 15;
    const int a_half = lane >> 4;
    uint32_t qh[2][4][4], ql[2][4][4];
#pragma unroll
    for (int mf = 0; mf < 2; mf++) {
        int gr = wq * 32 + mf * 16 + a_row;
        uint32_t hb = (gr < 64) ? 0u : (uint32_t)ABUF;
#pragma unroll
        for (int ks = 0; ks < 4; ks++) {
            uint32_t boff = (uint32_t)((gr & 63) * KST + ks * 16) * 2 + a_half * 16;
            ldm_x4(qh[mf][ks], uS + hb + boff);
            ldm_x4(ql[mf][ks], uS + 2*ABUF + hb + boff);
        }
    }
    __syncthreads();

    const int cr = tx >> 1;
    const int cc = (tx & 1) << 5;
    auto issue = [&](int kt, int s) {
        uint32_t sb = uS + s * ASTAGE;
#pragma unroll
        for (int t = 0; t < 4; t++) {
            int c8 = cc + t * 8;
            uint32_t so = (uint32_t)(cr * KST + c8) * 2;
            size_t g = base + (size_t)(kt * 64 + cr) * DHEAD + c8;
            cp16(sb + so,            g_khi + g);
            cp16(sb + ABUF   + so,   g_klo + g);
            cp16(sb + 2*ABUF + so,   g_vhi + g);
            cp16(sb + 3*ABUF + so,   g_vlo + g);
        }
        cp_commit();
    };

    float oacc[2][8][4];
#pragma unroll
    for (int mf = 0; mf < 2; mf++)
#pragma unroll
        for (int i = 0; i < 8; i++)
#pragma unroll
            for (int j = 0; j < 4; j++) oacc[mf][i][j] = 0.f;
    float mrow[4] = {-INFINITY, -INFINITY, -INFINITY, -INFINITY};
    float lrow[4] = {0.f, 0.f, 0.f, 0.f};

    const int b_row  = (lane & 7) + ((lane >> 4) << 3);
    const int b_half = (lane >> 3) & 1;
    const int v_mat  = lane >> 3;
    const int v_row  = lane & 7;
    const int ra     = lane >> 2;
    const int c_in   = 2 * (lane & 3);

    issue(0, 0);
    for (int kt = 0; kt < 16; kt++) {
        if (kt + 1 < 16) { issue(kt + 1, (kt + 1) & 1); cp_wait<1>(); }
        else             { cp_wait<0>(); }
        __syncthreads();

        const uint32_t sb = uS + (kt & 1) * ASTAGE;
        const uint32_t uKh = sb, uKl = sb + ABUF, uVh = sb + 2*ABUF, uVl = sb + 3*ABUF;

        float sacc[2][8][4];
#pragma unroll
        for (int mf = 0; mf < 2; mf++)
#pragma unroll
            for (int i = 0; i < 8; i++)
#pragma unroll
                for (int j = 0; j < 4; j++) sacc[mf][i][j] = 0.f;
#pragma unroll
        for (int nf2 = 0; nf2 < 4; nf2++) {
#pragma unroll
            for (int ks = 0; ks < 4; ks++) {
                uint32_t kh[4], kl[4];
                uint32_t boff = (uint32_t)((nf2 * 16 + b_row) * KST + ks * 16) * 2 + b_half * 16;
                ldm_x4(kh, uKh + boff);
                ldm_x4(kl, uKl + boff);
#pragma unroll
                for (int mf = 0; mf < 2; mf++) {
                    mma_bf16(sacc[mf][2*nf2],   qh[mf][ks], kh);
                    mma_bf16(sacc[mf][2*nf2+1], qh[mf][ks], kh + 2);
                    mma_bf16(sacc[mf][2*nf2],   qh[mf][ks], kl);
                    mma_bf16(sacc[mf][2*nf2+1], qh[mf][ks], kl + 2);
                    mma_bf16(sacc[mf][2*nf2],   ql[mf][ks], kh);
                    mma_bf16(sacc[mf][2*nf2+1], ql[mf][ks], kh + 2);
                }
            }
        }

        if ((kt >> 1) == blockIdx.x) {
#pragma unroll
            for (int mf = 0; mf < 2; mf++) {
                int row_a = q0 + wq * 32 + mf * 16 + ra;
                int row_b = row_a + 8;
#pragma unroll
                for (int nf = 0; nf < 8; nf++) {
                    int col = kt * 64 + nf * 8 + c_in;
                    if (col     == row_a) sacc[mf][nf][0] = -INFINITY;
                    if (col + 1 == row_a) sacc[mf][nf][1] = -INFINITY;
                    if (col     == row_b) sacc[mf][nf][2] = -INFINITY;
                    if (col + 1 == row_b) sacc[mf][nf][3] = -INFINITY;
                }
            }
        }

        float mt[4] = {-INFINITY, -INFINITY, -INFINITY, -INFINITY};
#pragma unroll
        for (int mf = 0; mf < 2; mf++)
#pragma unroll
            for (int nf = 0; nf < 8; nf++) {
                mt[2*mf]   = fmaxf(mt[2*mf],   fmaxf(sacc[mf][nf][0], sacc[mf][nf][1]));
                mt[2*mf+1] = fmaxf(mt[2*mf+1], fmaxf(sacc[mf][nf][2], sacc[mf][nf][3]));
            }
#pragma unroll
        for (int i = 0; i < 4; i++) {
            mt[i] = fmaxf(mt[i], __shfl_xor_sync(0xffffffffu, mt[i], 1));
            mt[i] = fmaxf(mt[i], __shfl_xor_sync(0xffffffffu, mt[i], 2));
        }

        float mn[4], ls[4] = {0.f, 0.f, 0.f, 0.f};
#pragma unroll
        for (int i = 0; i < 4; i++) mn[i] = fmaxf(mrow[i], mt[i]);
#pragma unroll
        for (int mf = 0; mf < 2; mf++)
#pragma unroll
            for (int nf = 0; nf < 8; nf++) {
                float p0 = ex2(sacc[mf][nf][0] - mn[2*mf]);
                float p1 = ex2(sacc[mf][nf][1] - mn[2*mf]);
                float p2 = ex2(sacc[mf][nf][2] - mn[2*mf+1]);
                float p3 = ex2(sacc[mf][nf][3] - mn[2*mf+1]);
                ls[2*mf] += p0 + p1; ls[2*mf+1] += p2 + p3;
                sacc[mf][nf][0] = p0; sacc[mf][nf][1] = p1;
                sacc[mf][nf][2] = p2; sacc[mf][nf][3] = p3;
            }
#pragma unroll
        for (int i = 0; i < 4; i++) {
            if (mn[i] > mrow[i]) {
                float cr_ = ex2(mrow[i] - mn[i]);     // 0 on first tile
                lrow[i] *= cr_;
                int mf = i >> 1, j0 = (i & 1) * 2;
#pragma unroll
                for (int nf = 0; nf < 8; nf++) {
                    oacc[mf][nf][j0]     *= cr_;
                    oacc[mf][nf][j0 + 1] *= cr_;
                }
                mrow[i] = mn[i];
            }
            lrow[i] += ls[i];
        }

#pragma unroll
        for (int kb = 0; kb < 4; kb++) {
            uint32_t pa_h[2][4], pa_l[2][4];
#pragma unroll
            for (int mf = 0; mf < 2; mf++) {
                pa_h[mf][0] = pack_hi(sacc[mf][2*kb][0],   sacc[mf][2*kb][1]);
                pa_h[mf][1] = pack_hi(sacc[mf][2*kb][2],   sacc[mf][2*kb][3]);
                pa_h[mf][2] = pack_hi(sacc[mf][2*kb+1][0], sacc[mf][2*kb+1][1]);
                pa_h[mf][3] = pack_hi(sacc[mf][2*kb+1][2], sacc[mf][2*kb+1][3]);
                pa_l[mf][0] = pack_lo(sacc[mf][2*kb][0],   sacc[mf][2*kb][1]);
                pa_l[mf][1] = pack_lo(sacc[mf][2*kb][2],   sacc[mf][2*kb][3]);
                pa_l[mf][2] = pack_lo(sacc[mf][2*kb+1][0], sacc[mf][2*kb+1][1]);
                pa_l[mf][3] = pack_lo(sacc[mf][2*kb+1][2], sacc[mf][2*kb+1][3]);
            }
#pragma unroll
            for (int nf2 = 0; nf2 < 4; nf2++) {
                uint32_t boff = (uint32_t)((kb * 16 + (v_mat & 1) * 8 + v_row) * KST
                                           + nf2 * 16 + (v_mat >> 1) * 8) * 2;
                uint32_t vh[4], vl[4];
                ldm_x4t(vh, uVh + boff);
                ldm_x4t(vl, uVl + boff);
#pragma unroll
                for (int mf = 0; mf < 2; mf++) {
                    mma_bf16(oacc[mf][2*nf2],   pa_h[mf], vh);
                    mma_bf16(oacc[mf][2*nf2+1], pa_h[mf], vh + 2);
                    mma_bf16(oacc[mf][2*nf2],   pa_h[mf], vl);
                    mma_bf16(oacc[mf][2*nf2+1], pa_h[mf], vl + 2);
                    mma_bf16(oacc[mf][2*nf2],   pa_l[mf], vh);
                    mma_bf16(oacc[mf][2*nf2+1], pa_l[mf], vh + 2);
                }
            }
        }
        __syncthreads();
    }

#pragma unroll
    for (int i = 0; i < 4; i++) {
        lrow[i] += __shfl_xor_sync(0xffffffffu, lrow[i], 1);
        lrow[i] += __shfl_xor_sync(0xffffffffu, lrow[i], 2);
    }

    const int b_ = bh >> 3, h = bh & 7;
#pragma unroll
    for (int mf = 0; mf < 2; mf++) {
        int row_a = q0 + wq * 32 + mf * 16 + ra;
        float inv0 = 1.f / lrow[2*mf], inv1 = 1.f / lrow[2*mf+1];
#pragma unroll
        for (int nf = 0; nf < 8; nf++) {
            int col = h * DHEAD + nf * 8 + c_in;
            size_t o0 = (size_t)(b_ * SEQ + row_a) * INNER + col;
            size_t o1 = (size_t)(b_ * SEQ + row_a + 8) * INNER + col;
            float a0 = oacc[mf][nf][0] * inv0, a1 = oacc[mf][nf][1] * inv0;
            float a2 = oacc[mf][nf][2] * inv1, a3 = oacc[mf][nf][3] * inv1;
            *(uint32_t*)&g_aohi[o0] = pack_hi(a0, a1);
            *(uint32_t*)&g_aolo[o0] = pack_lo(a0, a1);
            *(uint32_t*)&g_aohi[o1] = pack_hi(a2, a3);
            *(uint32_t*)&g_aolo[o1] = pack_lo(a2, a3);
        }
    }
}

// ============================================================================
extern "C" void kernel_launch(void* const* d_in, const int* in_sizes, int n_in,
                              void* d_out, int out_size)
{
    const float* x    = nullptr;
    const float* wqkv = nullptr;
    const float* wout = nullptr;
    const float* temp = nullptr;
    for (int i = 0; i < n_in; i++) {
        switch (in_sizes[i]) {
            case 4194304: x    = (const float*)d_in[i]; break;
            case 786432:  wqkv = (const float*)d_in[i]; break;
            case 262144:  wout = (const float*)d_in[i]; break;
            case 1:       temp = (const float*)d_in[i]; break;
            default: break;
        }
    }
    float* out = (float*)d_out;

    static int attr_done = 0;
    if (!attr_done) {
        cudaFuncSetAttribute(gemm_hmma_kernel,
                             cudaFuncAttributeMaxDynamicSharedMemorySize, 2 * GSTAGE);
        cudaFuncSetAttribute(attn_hmma_kernel,
                             cudaFuncAttributeMaxDynamicSharedMemorySize, 2 * ASTAGE);
        attr_done = 1;
    }

    __nv_bfloat16 *wq_hi, *wq_lo, *wo_hi, *wo_lo, *xhi, *xlo, *aohi, *aolo;
    cudaGetSymbolAddress((void**)&wq_hi, g_wqkv_hi);
    cudaGetSymbolAddress((void**)&wq_lo, g_wqkv_lo);
    cudaGetSymbolAddress((void**)&wo_hi, g_wout_hi);
    cudaGetSymbolAddress((void**)&wo_lo, g_wout_lo);
    cudaGetSymbolAddress((void**)&xhi,  g_xhi);
    cudaGetSymbolAddress((void**)&xlo,  g_xlo);
    cudaGetSymbolAddress((void**)&aohi, g_aohi);
    cudaGetSymbolAddress((void**)&aolo, g_aolo);

    xsplit_kernel<<<M_TOT * DIM / (256 * 4), 256>>>(x);
    wsplit_kernel<<<dim3(48, 16), dim3(32, 32)>>>(wqkv, wq_hi, wq_lo, 3 * INNER);
    wsplit_kernel<<<dim3(16, 16), dim3(32, 32)>>>(wout, wo_hi, wo_lo, INNER);

    gemm_hmma_kernel<<<dim3(12, 64), 128, 2 * GSTAGE>>>(xhi, xlo, wq_hi, wq_lo,
                                                        nullptr, temp, 0);
    attn_hmma_kernel<<<dim3(8, 64), 128, 2 * ASTAGE>>>();
    gemm_hmma_kernel<<<dim3(4, 64), 128, 2 * GSTAGE>>>(aohi, aolo, wo_hi, wo_lo,
                                                       out, temp, 1);
    (void)out_size;
}

// round 11
// speedup vs baseline: 1.5333x; 1.5333x over previous
#include <cuda_runtime.h>
#include <cuda_bf16.h>
#include <cuda_fp16.h>
#include <math.h>
#include <stdint.h>

#define NB      8
#define SEQ     1024
#define DIM     512
#define NHEADS  8
#define DHEAD   64
#define INNER   512
#define M_TOT   (NB*SEQ)        /* 8192 */
#define BH      (NB*NHEADS)     /* 64 */

// ---- scratch (allocation-free: __device__ globals) ----
__device__ __nv_bfloat16 g_xhi [(size_t)M_TOT*DIM];     // pre-split x
__device__ __nv_bfloat16 g_xlo [(size_t)M_TOT*DIM];
__device__ __nv_bfloat16 g_aohi[(size_t)M_TOT*INNER];   // attn out, split bf16
__device__ __nv_bfloat16 g_aolo[(size_t)M_TOT*INNER];
// fp16 attention operands, [bh][n][d]; q has exp(temperature)*log2(e) folded
__device__ __half g_q16hi[(size_t)BH*SEQ*DHEAD];
__device__ __half g_q16lo[(size_t)BH*SEQ*DHEAD];
__device__ __half g_k16  [(size_t)BH*SEQ*DHEAD];
__device__ __half g_v16  [(size_t)BH*SEQ*DHEAD];
// pre-transposed + split weights: [n][k] bf16
__device__ __nv_bfloat16 g_wqkv_hi[(size_t)3*INNER*DIM];
__device__ __nv_bfloat16 g_wqkv_lo[(size_t)3*INNER*DIM];
__device__ __nv_bfloat16 g_wout_hi[(size_t)DIM*INNER];
__device__ __nv_bfloat16 g_wout_lo[(size_t)DIM*INNER];

// ========================== helpers ===========================
__device__ __forceinline__ uint32_t smem_u32(const void* p) {
    uint32_t a;
    asm("{ .reg .u64 t; cvta.to.shared.u64 t, %1; cvt.u32.u64 %0, t; }" : "=r"(a) : "l"(p));
    return a;
}
__device__ __forceinline__ void ldm_x4(uint32_t* f, uint32_t addr) {
    asm volatile("ldmatrix.sync.aligned.m8n8.x4.shared.b16 {%0,%1,%2,%3}, [%4];"
                 : "=r"(f[0]), "=r"(f[1]), "=r"(f[2]), "=r"(f[3]) : "r"(addr));
}
__device__ __forceinline__ void ldm_x4t(uint32_t* f, uint32_t addr) {
    asm volatile("ldmatrix.sync.aligned.m8n8.x4.trans.shared.b16 {%0,%1,%2,%3}, [%4];"
                 : "=r"(f[0]), "=r"(f[1]), "=r"(f[2]), "=r"(f[3]) : "r"(addr));
}
__device__ __forceinline__ void mma_bf16(float* d, const uint32_t* a, const uint32_t* b) {
    asm("mma.sync.aligned.m16n8k16.row.col.f32.bf16.bf16.f32 "
        "{%0,%1,%2,%3}, {%4,%5,%6,%7}, {%8,%9}, {%0,%1,%2,%3};"
        : "+f"(d[0]), "+f"(d[1]), "+f"(d[2]), "+f"(d[3])
        : "r"(a[0]), "r"(a[1]), "r"(a[2]), "r"(a[3]), "r"(b[0]), "r"(b[1]));
}
__device__ __forceinline__ void mma_fp16(float* d, const uint32_t* a, const uint32_t* b) {
    asm("mma.sync.aligned.m16n8k16.row.col.f32.f16.f16.f32 "
        "{%0,%1,%2,%3}, {%4,%5,%6,%7}, {%8,%9}, {%0,%1,%2,%3};"
        : "+f"(d[0]), "+f"(d[1]), "+f"(d[2]), "+f"(d[3])
        : "r"(a[0]), "r"(a[1]), "r"(a[2]), "r"(a[3]), "r"(b[0]), "r"(b[1]));
}
__device__ __forceinline__ uint32_t pack_hi(float x, float y) {
    __nv_bfloat162 h = {__float2bfloat16(x), __float2bfloat16(y)};
    return *(uint32_t*)&h;
}
__device__ __forceinline__ uint32_t pack_lo(float x, float y) {
    float rx = x - __bfloat162float(__float2bfloat16(x));
    float ry = y - __bfloat162float(__float2bfloat16(y));
    __nv_bfloat162 l = {__float2bfloat16(rx), __float2bfloat16(ry)};
    return *(uint32_t*)&l;
}
__device__ __forceinline__ uint32_t pack_h2(float x, float y) {
    __half2 h = __floats2half2_rn(x, y);
    return *(uint32_t*)&h;
}
__device__ __forceinline__ uint32_t pack_h2_lo(float x, float y) {
    float rx = x - __half2float(__float2half_rn(x));
    float ry = y - __half2float(__float2half_rn(y));
    __half2 h = __floats2half2_rn(rx, ry);
    return *(uint32_t*)&h;
}
// hardware EX2 (MUFU); ex2(-inf)=0
__device__ __forceinline__ float ex2(float x) {
    float y;
    asm("ex2.approx.f32 %0, %1;" : "=f"(y) : "f"(x));
    return y;
}
__device__ __forceinline__ void cp16(uint32_t sdst, const void* gsrc) {
    asm volatile("cp.async.cg.shared.global [%0], [%1], 16;" :: "r"(sdst), "l"(gsrc));
}
__device__ __forceinline__ void cp_commit() { asm volatile("cp.async.commit_group;"); }
template <int N> __device__ __forceinline__ void cp_wait() {
    asm volatile("cp.async.wait_group %0;" :: "n"(N));
}

// ============================================================================
// Prep kernels
// ============================================================================
__global__ __launch_bounds__(256) void xsplit_kernel(const float* __restrict__ X)
{
    size_t i = ((size_t)blockIdx.x * 256 + threadIdx.x) * 4;
    float4 v = *(const float4*)&X[i];
    *(uint2*)&g_xhi[i] = make_uint2(pack_hi(v.x, v.y), pack_hi(v.z, v.w));
    *(uint2*)&g_xlo[i] = make_uint2(pack_lo(v.x, v.y), pack_lo(v.z, v.w));
}

__global__ void wsplit_kernel(const float* __restrict__ W,
                              __nv_bfloat16* __restrict__ hi,
                              __nv_bfloat16* __restrict__ lo, int N)
{
    __shared__ float t[32][33];
    int n = blockIdx.x * 32 + threadIdx.x;
    int k = blockIdx.y * 32 + threadIdx.y;
    t[threadIdx.y][threadIdx.x] = W[(size_t)k * N + n];
    __syncthreads();
    int n2 = blockIdx.x * 32 + threadIdx.y;
    int k2 = blockIdx.y * 32 + threadIdx.x;
    float v = t[threadIdx.x][threadIdx.y];
    __nv_bfloat16 h = __float2bfloat16(v);
    hi[(size_t)n2 * DIM + k2] = h;
    lo[(size_t)n2 * DIM + k2] = __float2bfloat16(v - __bfloat162float(h));
}

// ============================================================================
// HMMA GEMM (R9 config: 256 thr, 8 warps 4x2, warp 32x64, BK=32, bf16 3-MMA)
// mode 0: epilogue emits fp16 q(split,scaled)/k/v; mode 1: fp32 C.
// ============================================================================
#define BK   32
#define PAD  40
#define GST  10240
#define GSTAGE (4*GST)

__global__ __launch_bounds__(256, 2) void gemm_hmma_kernel(
    const __nv_bfloat16* __restrict__ Ahi,
    const __nv_bfloat16* __restrict__ Alo,
    const __nv_bfloat16* __restrict__ Bhi,
    const __nv_bfloat16* __restrict__ Blo,
    float* __restrict__ C, const float* __restrict__ temp, int mode)
{
    extern __shared__ char smem[];
    const uint32_t uS = smem_u32(smem);

    const int tx   = threadIdx.x;
    const int lane = tx & 31;
    const int wid  = tx >> 5;
    const int wm   = wid >> 1;
    const int wn   = wid & 1;
    const int row0 = blockIdx.y * 128;
    const int col0 = blockIdx.x * 128;

    const int cr = tx >> 2;
    const int cc = (tx & 3) << 3;
    auto issue = [&](int kc, int s) {
        uint32_t sb = uS + s * GSTAGE;
#pragma unroll
        for (int t = 0; t < 2; t++) {
            int r = cr + t * 64;
            uint32_t so = (uint32_t)(r * PAD + cc) * 2;
            size_t  ga = (size_t)(row0 + r) * DIM + kc + cc;
            size_t  gb = (size_t)(col0 + r) * DIM + kc + cc;
            cp16(sb + so,           Ahi + ga);
            cp16(sb + GST   + so,   Alo + ga);
            cp16(sb + 2*GST + so,   Bhi + gb);
            cp16(sb + 3*GST + so,   Blo + gb);
        }
        cp_commit();
    };

    float acc[2][8][4];
#pragma unroll
    for (int i = 0; i < 2; i++)
#pragma unroll
        for (int j = 0; j < 8; j++)
#pragma unroll
            for (int t = 0; t < 4; t++) acc[i][j][t] = 0.f;

    const int a_row  = lane & 15;
    const int a_half = lane >> 4;
    const int b_row  = (lane & 7) + ((lane >> 4) << 3);
    const int b_half = (lane >> 3) & 1;

    issue(0, 0);
    const int KITER = DIM / BK;
    for (int kc = 0; kc < KITER; kc++) {
        if (kc + 1 < KITER) { issue((kc + 1) * BK, (kc + 1) & 1); cp_wait<1>(); }
        else                { cp_wait<0>(); }
        __syncthreads();

        const uint32_t sb = uS + (kc & 1) * GSTAGE;
        const uint32_t uAhi = sb, uAlo = sb + GST, uBhi = sb + 2*GST, uBlo = sb + 3*GST;
#pragma unroll
        for (int kk = 0; kk < 2; kk++) {
            uint32_t afh[2][4], afl[2][4];
#pragma unroll
            for (int mf = 0; mf < 2; mf++) {
                uint32_t boff = (uint32_t)((wm * 32 + mf * 16 + a_row) * PAD + kk * 16) * 2
                              + a_half * 16;
                ldm_x4(afh[mf], uAhi + boff);
                ldm_x4(afl[mf], uAlo + boff);
            }
            uint32_t bfh[8][2], bfl[8][2];
#pragma unroll
            for (int nf2 = 0; nf2 < 4; nf2++) {
                uint32_t boff = (uint32_t)((wn * 64 + nf2 * 16 + b_row) * PAD + kk * 16) * 2
                              + b_half * 16;
                uint32_t th[4], tl[4];
                ldm_x4(th, uBhi + boff);
                ldm_x4(tl, uBlo + boff);
                bfh[nf2*2][0] = th[0]; bfh[nf2*2][1] = th[1];
                bfh[nf2*2+1][0] = th[2]; bfh[nf2*2+1][1] = th[3];
                bfl[nf2*2][0] = tl[0]; bfl[nf2*2][1] = tl[1];
                bfl[nf2*2+1][0] = tl[2]; bfl[nf2*2+1][1] = tl[3];
            }
#pragma unroll
            for (int mf = 0; mf < 2; mf++)
#pragma unroll
                for (int nf = 0; nf < 8; nf++)
                    mma_bf16(acc[mf][nf], afh[mf], bfh[nf]);
#pragma unroll
            for (int mf = 0; mf < 2; mf++)
#pragma unroll
                for (int nf = 0; nf < 8; nf++)
                    mma_bf16(acc[mf][nf], afh[mf], bfl[nf]);
#pragma unroll
            for (int mf = 0; mf < 2; mf++)
#pragma unroll
                for (int nf = 0; nf < 8; nf++)
                    mma_bf16(acc[mf][nf], afl[mf], bfh[nf]);
        }
        __syncthreads();
    }

    // q pre-scale: exp(temperature)*log2(e) -> attention works in log2 domain
    const float sc = (mode == 0) ? __expf(*temp) * 1.44269504f : 1.f;
#pragma unroll
    for (int mf = 0; mf < 2; mf++) {
        int m_base = row0 + wm * 32 + mf * 16 + (lane >> 2);
#pragma unroll
        for (int nf = 0; nf < 8; nf++) {
            int c = col0 + wn * 64 + nf * 8 + 2 * (lane & 3);
            float2 v0 = make_float2(acc[mf][nf][0], acc[mf][nf][1]);
            float2 v1 = make_float2(acc[mf][nf][2], acc[mf][nf][3]);
            if (mode == 1) {
                *(float2*)&C[(size_t)m_base * DIM + c]       = v0;
                *(float2*)&C[(size_t)(m_base + 8) * DIM + c] = v1;
            } else {
                int which = c >> 9;
                int inner = c & 511;
                int h     = inner >> 6;
                int d     = inner & 63;
                int b0 = m_base >> 10, n0 = m_base & 1023;
                int m1 = m_base + 8;
                int b1 = m1 >> 10, n1 = m1 & 1023;
                size_t off0 = ((size_t)((b0 * NHEADS + h) * SEQ + n0)) * DHEAD + d;
                size_t off1 = ((size_t)((b1 * NHEADS + h) * SEQ + n1)) * DHEAD + d;
                if (which == 0) {
                    v0.x *= sc; v0.y *= sc; v1.x *= sc; v1.y *= sc;
                    *(uint32_t*)&g_q16hi[off0] = pack_h2(v0.x, v0.y);
                    *(uint32_t*)&g_q16lo[off0] = pack_h2_lo(v0.x, v0.y);
                    *(uint32_t*)&g_q16hi[off1] = pack_h2(v1.x, v1.y);
                    *(uint32_t*)&g_q16lo[off1] = pack_h2_lo(v1.x, v1.y);
                } else if (which == 1) {
                    *(uint32_t*)&g_k16[off0] = pack_h2(v0.x, v0.y);
                    *(uint32_t*)&g_k16[off1] = pack_h2(v1.x, v1.y);
                } else {
                    *(uint32_t*)&g_v16[off0] = pack_h2(v0.x, v0.y);
                    *(uint32_t*)&g_v16[off1] = pack_h2(v1.x, v1.y);
                }
            }
        }
    }
}

// ============================================================================
// Flash attention fp16: q-block 128, 4 warps x 32 q-rows, K-tiles 64.
// QK: Q split fp16 (2 MMA), K single. PV: P single fp16, V single (1 MMA).
// 2-stage cp.async (K,V only), EX2 softmax. Output: bf16 hi/lo split.
// ============================================================================
#define KST   72
#define ABUF  9216                 /* 64*KST*2 bytes */
#define ASTAGE (2*ABUF)            /* K, V */

__global__ __launch_bounds__(128, 2) void attn_hmma_kernel()
{
    extern __shared__ char smem[];
    const uint32_t uS = smem_u32(smem);

    const int tx   = threadIdx.x;
    const int lane = tx & 31;
    const int wq   = tx >> 5;
    const int bh   = blockIdx.y;
    const int q0   = blockIdx.x * 128;
    const size_t base = (size_t)bh * SEQ * DHEAD;

    // ---- stage Q (128 rows, hi+lo fp16) across the 4 ABUF regions ----
    // qhi rows 0-63 -> buf0, rows 64-127 -> buf1; qlo -> buf2, buf3
#pragma unroll
    for (int t = 0; t < 8; t++) {
        int id = tx + t * 128;
        int r  = id >> 3, c8 = (id & 7) << 3;
        uint32_t hb = (r < 64) ? 0u : (uint32_t)ABUF;
        uint32_t so = (uint32_t)((r & 63) * KST + c8) * 2;
        *(uint4*)(smem + hb + so)          = *(const uint4*)&g_q16hi[base + (size_t)(q0 + r) * DHEAD + c8];
        *(uint4*)(smem + 2*ABUF + hb + so) = *(const uint4*)&g_q16lo[base + (size_t)(q0 + r) * DHEAD + c8];
    }
    __syncthreads();

    const int a_row  = lane & 15;
    const int a_half = lane >> 4;
    uint32_t qh[2][4][4], ql[2][4][4];
#pragma unroll
    for (int mf = 0; mf < 2; mf++) {
        int gr = wq * 32 + mf * 16 + a_row;
        uint32_t hb = (gr < 64) ? 0u : (uint32_t)ABUF;
#pragma unroll
        for (int ks = 0; ks < 4; ks++) {
            uint32_t boff = (uint32_t)((gr & 63) * KST + ks * 16) * 2 + a_half * 16;
            ldm_x4(qh[mf][ks], uS + hb + boff);
            ldm_x4(ql[mf][ks], uS + 2*ABUF + hb + boff);
        }
    }
    __syncthreads();

    const int cr = tx >> 1;
    const int cc = (tx & 1) << 5;
    auto issue = [&](int kt, int s) {
        uint32_t sb = uS + s * ASTAGE;
#pragma unroll
        for (int t = 0; t < 4; t++) {
            int c8 = cc + t * 8;
            uint32_t so = (uint32_t)(cr * KST + c8) * 2;
            size_t g = base + (size_t)(kt * 64 + cr) * DHEAD + c8;
            cp16(sb + so,          g_k16 + g);
            cp16(sb + ABUF + so,   g_v16 + g);
        }
        cp_commit();
    };

    float oacc[2][8][4];
#pragma unroll
    for (int mf = 0; mf < 2; mf++)
#pragma unroll
        for (int i = 0; i < 8; i++)
#pragma unroll
            for (int j = 0; j < 4; j++) oacc[mf][i][j] = 0.f;
    float mrow[4] = {-INFINITY, -INFINITY, -INFINITY, -INFINITY};
    float lrow[4] = {0.f, 0.f, 0.f, 0.f};

    const int b_row  = (lane & 7) + ((lane >> 4) << 3);
    const int b_half = (lane >> 3) & 1;
    const int v_mat  = lane >> 3;
    const int v_row  = lane & 7;
    const int ra     = lane >> 2;
    const int c_in   = 2 * (lane & 3);

    issue(0, 0);
    for (int kt = 0; kt < 16; kt++) {
        if (kt + 1 < 16) { issue(kt + 1, (kt + 1) & 1); cp_wait<1>(); }
        else             { cp_wait<0>(); }
        __syncthreads();

        const uint32_t sb = uS + (kt & 1) * ASTAGE;
        const uint32_t uKh = sb, uVh = sb + ABUF;

        // ---- S = Q K^T: Q split 2-MMA, K single ----
        float sacc[2][8][4];
#pragma unroll
        for (int mf = 0; mf < 2; mf++)
#pragma unroll
            for (int i = 0; i < 8; i++)
#pragma unroll
                for (int j = 0; j < 4; j++) sacc[mf][i][j] = 0.f;
#pragma unroll
        for (int nf2 = 0; nf2 < 4; nf2++) {
#pragma unroll
            for (int ks = 0; ks < 4; ks++) {
                uint32_t kh[4];
                uint32_t boff = (uint32_t)((nf2 * 16 + b_row) * KST + ks * 16) * 2 + b_half * 16;
                ldm_x4(kh, uKh + boff);
#pragma unroll
                for (int mf = 0; mf < 2; mf++) {
                    mma_fp16(sacc[mf][2*nf2],   qh[mf][ks], kh);
                    mma_fp16(sacc[mf][2*nf2+1], qh[mf][ks], kh + 2);
                    mma_fp16(sacc[mf][2*nf2],   ql[mf][ks], kh);
                    mma_fp16(sacc[mf][2*nf2+1], ql[mf][ks], kh + 2);
                }
            }
        }

        // ---- diagonal mask ----
        if ((kt >> 1) == blockIdx.x) {
#pragma unroll
            for (int mf = 0; mf < 2; mf++) {
                int row_a = q0 + wq * 32 + mf * 16 + ra;
                int row_b = row_a + 8;
#pragma unroll
                for (int nf = 0; nf < 8; nf++) {
                    int col = kt * 64 + nf * 8 + c_in;
                    if (col     == row_a) sacc[mf][nf][0] = -INFINITY;
                    if (col + 1 == row_a) sacc[mf][nf][1] = -INFINITY;
                    if (col     == row_b) sacc[mf][nf][2] = -INFINITY;
                    if (col + 1 == row_b) sacc[mf][nf][3] = -INFINITY;
                }
            }
        }

        // ---- online softmax (base-2, MUFU EX2) ----
        float mt[4] = {-INFINITY, -INFINITY, -INFINITY, -INFINITY};
#pragma unroll
        for (int mf = 0; mf < 2; mf++)
#pragma unroll
            for (int nf = 0; nf < 8; nf++) {
                mt[2*mf]   = fmaxf(mt[2*mf],   fmaxf(sacc[mf][nf][0], sacc[mf][nf][1]));
                mt[2*mf+1] = fmaxf(mt[2*mf+1], fmaxf(sacc[mf][nf][2], sacc[mf][nf][3]));
            }
#pragma unroll
        for (int i = 0; i < 4; i++) {
            mt[i] = fmaxf(mt[i], __shfl_xor_sync(0xffffffffu, mt[i], 1));
            mt[i] = fmaxf(mt[i], __shfl_xor_sync(0xffffffffu, mt[i], 2));
        }

        float mn[4], ls[4] = {0.f, 0.f, 0.f, 0.f};
#pragma unroll
        for (int i = 0; i < 4; i++) mn[i] = fmaxf(mrow[i], mt[i]);
#pragma unroll
        for (int mf = 0; mf < 2; mf++)
#pragma unroll
            for (int nf = 0; nf < 8; nf++) {
                float p0 = ex2(sacc[mf][nf][0] - mn[2*mf]);
                float p1 = ex2(sacc[mf][nf][1] - mn[2*mf]);
                float p2 = ex2(sacc[mf][nf][2] - mn[2*mf+1]);
                float p3 = ex2(sacc[mf][nf][3] - mn[2*mf+1]);
                ls[2*mf] += p0 + p1; ls[2*mf+1] += p2 + p3;
                sacc[mf][nf][0] = p0; sacc[mf][nf][1] = p1;
                sacc[mf][nf][2] = p2; sacc[mf][nf][3] = p3;
            }
#pragma unroll
        for (int i = 0; i < 4; i++) {
            if (mn[i] > mrow[i]) {
                float cr_ = ex2(mrow[i] - mn[i]);
                lrow[i] *= cr_;
                int mf = i >> 1, j0 = (i & 1) * 2;
#pragma unroll
                for (int nf = 0; nf < 8; nf++) {
                    oacc[mf][nf][j0]     *= cr_;
                    oacc[mf][nf][j0 + 1] *= cr_;
                }
                mrow[i] = mn[i];
            }
            lrow[i] += ls[i];
        }

        // ---- O += P V: P single fp16, V single (1 MMA) ----
#pragma unroll
        for (int kb = 0; kb < 4; kb++) {
            uint32_t pa[2][4];
#pragma unroll
            for (int mf = 0; mf < 2; mf++) {
                pa[mf][0] = pack_h2(sacc[mf][2*kb][0],   sacc[mf][2*kb][1]);
                pa[mf][1] = pack_h2(sacc[mf][2*kb][2],   sacc[mf][2*kb][3]);
                pa[mf][2] = pack_h2(sacc[mf][2*kb+1][0], sacc[mf][2*kb+1][1]);
                pa[mf][3] = pack_h2(sacc[mf][2*kb+1][2], sacc[mf][2*kb+1][3]);
            }
#pragma unroll
            for (int nf2 = 0; nf2 < 4; nf2++) {
                uint32_t boff = (uint32_t)((kb * 16 + (v_mat & 1) * 8 + v_row) * KST
                                           + nf2 * 16 + (v_mat >> 1) * 8) * 2;
                uint32_t vh[4];
                ldm_x4t(vh, uVh + boff);
#pragma unroll
                for (int mf = 0; mf < 2; mf++) {
                    mma_fp16(oacc[mf][2*nf2],   pa[mf], vh);
                    mma_fp16(oacc[mf][2*nf2+1], pa[mf], vh + 2);
                }
            }
        }
        __syncthreads();
    }

    // ---- finalize: write bf16 hi/lo for the out-projection ----
#pragma unroll
    for (int i = 0; i < 4; i++) {
        lrow[i] += __shfl_xor_sync(0xffffffffu, lrow[i], 1);
        lrow[i] += __shfl_xor_sync(0xffffffffu, lrow[i], 2);
    }

    const int b_ = bh >> 3, h = bh & 7;
#pragma unroll
    for (int mf = 0; mf < 2; mf++) {
        int row_a = q0 + wq * 32 + mf * 16 + ra;
        float inv0 = 1.f / lrow[2*mf], inv1 = 1.f / lrow[2*mf+1];
#pragma unroll
        for (int nf = 0; nf < 8; nf++) {
            int col = h * DHEAD + nf * 8 + c_in;
            size_t o0 = (size_t)(b_ * SEQ + row_a) * INNER + col;
            size_t o1 = (size_t)(b_ * SEQ + row_a + 8) * INNER + col;
            float a0 = oacc[mf][nf][0] * inv0, a1 = oacc[mf][nf][1] * inv0;
            float a2 = oacc[mf][nf][2] * inv1, a3 = oacc[mf][nf][3] * inv1;
            *(uint32_t*)&g_aohi[o0] = pack_hi(a0, a1);
            *(uint32_t*)&g_aolo[o0] = pack_lo(a0, a1);
            *(uint32_t*)&g_aohi[o1] = pack_hi(a2, a3);
            *(uint32_t*)&g_aolo[o1] = pack_lo(a2, a3);
        }
    }
}

// ============================================================================
extern "C" void kernel_launch(void* const* d_in, const int* in_sizes, int n_in,
                              void* d_out, int out_size)
{
    const float* x    = nullptr;
    const float* wqkv = nullptr;
    const float* wout = nullptr;
    const float* temp = nullptr;
    for (int i = 0; i < n_in; i++) {
        switch (in_sizes[i]) {
            case 4194304: x    = (const float*)d_in[i]; break;
            case 786432:  wqkv = (const float*)d_in[i]; break;
            case 262144:  wout = (const float*)d_in[i]; break;
            case 1:       temp = (const float*)d_in[i]; break;
            default: break;
        }
    }
    float* out = (float*)d_out;

    static int attr_done = 0;
    if (!attr_done) {
        cudaFuncSetAttribute(gemm_hmma_kernel,
                             cudaFuncAttributeMaxDynamicSharedMemorySize, 2 * GSTAGE);
        cudaFuncSetAttribute(attn_hmma_kernel,
                             cudaFuncAttributeMaxDynamicSharedMemorySize, 2 * ASTAGE);
        attr_done = 1;
    }

    __nv_bfloat16 *wq_hi, *wq_lo, *wo_hi, *wo_lo, *xhi, *xlo, *aohi, *aolo;
    cudaGetSymbolAddress((void**)&wq_hi, g_wqkv_hi);
    cudaGetSymbolAddress((void**)&wq_lo, g_wqkv_lo);
    cudaGetSymbolAddress((void**)&wo_hi, g_wout_hi);
    cudaGetSymbolAddress((void**)&wo_lo, g_wout_lo);
    cudaGetSymbolAddress((void**)&xhi,  g_xhi);
    cudaGetSymbolAddress((void**)&xlo,  g_xlo);
    cudaGetSymbolAddress((void**)&aohi, g_aohi);
    cudaGetSymbolAddress((void**)&aolo, g_aolo);

    xsplit_kernel<<<M_TOT * DIM / (256 * 4), 256>>>(x);
    wsplit_kernel<<<dim3(48, 16), dim3(32, 32)>>>(wqkv, wq_hi, wq_lo, 3 * INNER);
    wsplit_kernel<<<dim3(16, 16), dim3(32, 32)>>>(wout, wo_hi, wo_lo, INNER);

    gemm_hmma_kernel<<<dim3(12, 64), 256, 2 * GSTAGE>>>(xhi, xlo, wq_hi, wq_lo,
                                                        nullptr, temp, 0);
    attn_hmma_kernel<<<dim3(8, 64), 128, 2 * ASTAGE>>>();
    gemm_hmma_kernel<<<dim3(4, 64), 256, 2 * GSTAGE>>>(aohi, aolo, wo_hi, wo_lo,
                                                       out, temp, 1);
    (void)out_size;
}

// round 12
// speedup vs baseline: 1.8840x; 1.2287x over previous
#include <cuda_runtime.h>
#include <cuda_bf16.h>
#include <cuda_fp16.h>
#include <math.h>
#include <stdint.h>

#define NB      8
#define SEQ     1024
#define DIM     512
#define NHEADS  8
#define DHEAD   64
#define INNER   512
#define M_TOT   (NB*SEQ)        /* 8192 */
#define BH      (NB*NHEADS)     /* 64 */

// ---- scratch (allocation-free: __device__ globals), all fp16 now ----
__device__ __half g_x16hi [(size_t)M_TOT*DIM];     // split x
__device__ __half g_x16lo [(size_t)M_TOT*DIM];
__device__ __half g_ao16hi[(size_t)M_TOT*INNER];   // split attention output
__device__ __half g_ao16lo[(size_t)M_TOT*INNER];
// attention operands, [bh][n][d]; q has exp(temperature)*log2(e) folded in
__device__ __half g_q16hi[(size_t)BH*SEQ*DHEAD];
__device__ __half g_q16lo[(size_t)BH*SEQ*DHEAD];
__device__ __half g_k16  [(size_t)BH*SEQ*DHEAD];
__device__ __half g_v16  [(size_t)BH*SEQ*DHEAD];
// pre-transposed single-fp16 weights: [n][k]
__device__ __half g_w16qkv[(size_t)3*INNER*DIM];
__device__ __half g_w16out[(size_t)DIM*INNER];

// ========================== helpers ===========================
__device__ __forceinline__ uint32_t smem_u32(const void* p) {
    uint32_t a;
    asm("{ .reg .u64 t; cvta.to.shared.u64 t, %1; cvt.u32.u64 %0, t; }" : "=r"(a) : "l"(p));
    return a;
}
__device__ __forceinline__ void ldm_x4(uint32_t* f, uint32_t addr) {
    asm volatile("ldmatrix.sync.aligned.m8n8.x4.shared.b16 {%0,%1,%2,%3}, [%4];"
                 : "=r"(f[0]), "=r"(f[1]), "=r"(f[2]), "=r"(f[3]) : "r"(addr));
}
__device__ __forceinline__ void ldm_x4t(uint32_t* f, uint32_t addr) {
    asm volatile("ldmatrix.sync.aligned.m8n8.x4.trans.shared.b16 {%0,%1,%2,%3}, [%4];"
                 : "=r"(f[0]), "=r"(f[1]), "=r"(f[2]), "=r"(f[3]) : "r"(addr));
}
__device__ __forceinline__ void mma_fp16(float* d, const uint32_t* a, const uint32_t* b) {
    asm("mma.sync.aligned.m16n8k16.row.col.f32.f16.f16.f32 "
        "{%0,%1,%2,%3}, {%4,%5,%6,%7}, {%8,%9}, {%0,%1,%2,%3};"
        : "+f"(d[0]), "+f"(d[1]), "+f"(d[2]), "+f"(d[3])
        : "r"(a[0]), "r"(a[1]), "r"(a[2]), "r"(a[3]), "r"(b[0]), "r"(b[1]));
}
__device__ __forceinline__ uint32_t pack_h2(float x, float y) {
    __half2 h = __floats2half2_rn(x, y);
    return *(uint32_t*)&h;
}
__device__ __forceinline__ uint32_t pack_h2_lo(float x, float y) {
    float rx = x - __half2float(__float2half_rn(x));
    float ry = y - __half2float(__float2half_rn(y));
    __half2 h = __floats2half2_rn(rx, ry);
    return *(uint32_t*)&h;
}
// hardware EX2 (MUFU); ex2(-inf)=0
__device__ __forceinline__ float ex2(float x) {
    float y;
    asm("ex2.approx.f32 %0, %1;" : "=f"(y) : "f"(x));
    return y;
}
__device__ __forceinline__ void cp16(uint32_t sdst, const void* gsrc) {
    asm volatile("cp.async.cg.shared.global [%0], [%1], 16;" :: "r"(sdst), "l"(gsrc));
}
__device__ __forceinline__ void cp_commit() { asm volatile("cp.async.commit_group;"); }
template <int N> __device__ __forceinline__ void cp_wait() {
    asm volatile("cp.async.wait_group %0;" :: "n"(N));
}

// ============================================================================
// Prep: split x fp32 -> fp16 hi/lo
// ============================================================================
__global__ __launch_bounds__(256) void xsplit_kernel(const float* __restrict__ X)
{
    size_t i = ((size_t)blockIdx.x * 256 + threadIdx.x) * 4;
    float4 v = *(const float4*)&X[i];
    *(uint2*)&g_x16hi[i] = make_uint2(pack_h2(v.x, v.y), pack_h2(v.z, v.w));
    *(uint2*)&g_x16lo[i] = make_uint2(pack_h2_lo(v.x, v.y), pack_h2_lo(v.z, v.w));
}

// ============================================================================
// Prep: transpose [512][N] fp32 -> [N][512] single fp16
// ============================================================================
__global__ void wconv_kernel(const float* __restrict__ W,
                             __half* __restrict__ out, int N)
{
    __shared__ float t[32][33];
    int n = blockIdx.x * 32 + threadIdx.x;
    int k = blockIdx.y * 32 + threadIdx.y;
    t[threadIdx.y][threadIdx.x] = W[(size_t)k * N + n];
    __syncthreads();
    int n2 = blockIdx.x * 32 + threadIdx.y;
    int k2 = blockIdx.y * 32 + threadIdx.x;
    out[(size_t)n2 * DIM + k2] = __float2half_rn(t[threadIdx.x][threadIdx.y]);
}

// ============================================================================
// HMMA GEMM fp16: 256 thr, 8 warps (4x2), warp 32x64, BK=32.
// Split-fp16 activations (2-MMA: ah*b + al*b) x single-fp16 weights.
// 3 smem buffers/stage (Ahi, Alo, B), 2-stage cp.async pipeline.
// mode 0: epilogue emits fp16 q(split,scaled)/k/v; mode 1: fp32 C.
// ============================================================================
#define BK   32
#define PAD  40
#define GST  10240
#define GSTAGE (3*GST)             /* Ahi, Alo, B */

__global__ __launch_bounds__(256, 2) void gemm_hmma_kernel(
    const __half* __restrict__ Ahi,
    const __half* __restrict__ Alo,
    const __half* __restrict__ B,
    float* __restrict__ C, const float* __restrict__ temp, int mode)
{
    extern __shared__ char smem[];
    const uint32_t uS = smem_u32(smem);

    const int tx   = threadIdx.x;
    const int lane = tx & 31;
    const int wid  = tx >> 5;
    const int wm   = wid >> 1;
    const int wn   = wid & 1;
    const int row0 = blockIdx.y * 128;
    const int col0 = blockIdx.x * 128;

    const int cr = tx >> 2;
    const int cc = (tx & 3) << 3;
    auto issue = [&](int kc, int s) {
        uint32_t sb = uS + s * GSTAGE;
#pragma unroll
        for (int t = 0; t < 2; t++) {
            int r = cr + t * 64;
            uint32_t so = (uint32_t)(r * PAD + cc) * 2;
            size_t  ga = (size_t)(row0 + r) * DIM + kc + cc;
            size_t  gb = (size_t)(col0 + r) * DIM + kc + cc;
            cp16(sb + so,           Ahi + ga);
            cp16(sb + GST   + so,   Alo + ga);
            cp16(sb + 2*GST + so,   B   + gb);
        }
        cp_commit();
    };

    float acc[2][8][4];
#pragma unroll
    for (int i = 0; i < 2; i++)
#pragma unroll
        for (int j = 0; j < 8; j++)
#pragma unroll
            for (int t = 0; t < 4; t++) acc[i][j][t] = 0.f;

    const int a_row  = lane & 15;
    const int a_half = lane >> 4;
    const int b_row  = (lane & 7) + ((lane >> 4) << 3);
    const int b_half = (lane >> 3) & 1;

    issue(0, 0);
    const int KITER = DIM / BK;        // 16
    for (int kc = 0; kc < KITER; kc++) {
        if (kc + 1 < KITER) { issue((kc + 1) * BK, (kc + 1) & 1); cp_wait<1>(); }
        else                { cp_wait<0>(); }
        __syncthreads();

        const uint32_t sb = uS + (kc & 1) * GSTAGE;
        const uint32_t uAhi = sb, uAlo = sb + GST, uB = sb + 2*GST;
#pragma unroll
        for (int kk = 0; kk < 2; kk++) {
            uint32_t afh[2][4], afl[2][4];
#pragma unroll
            for (int mf = 0; mf < 2; mf++) {
                uint32_t boff = (uint32_t)((wm * 32 + mf * 16 + a_row) * PAD + kk * 16) * 2
                              + a_half * 16;
                ldm_x4(afh[mf], uAhi + boff);
                ldm_x4(afl[mf], uAlo + boff);
            }
            uint32_t bf[8][2];
#pragma unroll
            for (int nf2 = 0; nf2 < 4; nf2++) {
                uint32_t boff = (uint32_t)((wn * 64 + nf2 * 16 + b_row) * PAD + kk * 16) * 2
                              + b_half * 16;
                uint32_t th[4];
                ldm_x4(th, uB + boff);
                bf[nf2*2][0] = th[0]; bf[nf2*2][1] = th[1];
                bf[nf2*2+1][0] = th[2]; bf[nf2*2+1][1] = th[3];
            }
            // hi sweep then lo sweep (16 independent accs between touches)
#pragma unroll
            for (int mf = 0; mf < 2; mf++)
#pragma unroll
                for (int nf = 0; nf < 8; nf++)
                    mma_fp16(acc[mf][nf], afh[mf], bf[nf]);
#pragma unroll
            for (int mf = 0; mf < 2; mf++)
#pragma unroll
                for (int nf = 0; nf < 8; nf++)
                    mma_fp16(acc[mf][nf], afl[mf], bf[nf]);
        }
        __syncthreads();
    }

    // q pre-scale: exp(temperature)*log2(e) -> attention works in log2 domain
    const float sc = (mode == 0) ? __expf(*temp) * 1.44269504f : 1.f;
#pragma unroll
    for (int mf = 0; mf < 2; mf++) {
        int m_base = row0 + wm * 32 + mf * 16 + (lane >> 2);
#pragma unroll
        for (int nf = 0; nf < 8; nf++) {
            int c = col0 + wn * 64 + nf * 8 + 2 * (lane & 3);
            float2 v0 = make_float2(acc[mf][nf][0], acc[mf][nf][1]);
            float2 v1 = make_float2(acc[mf][nf][2], acc[mf][nf][3]);
            if (mode == 1) {
                *(float2*)&C[(size_t)m_base * DIM + c]       = v0;
                *(float2*)&C[(size_t)(m_base + 8) * DIM + c] = v1;
            } else {
                int which = c >> 9;
                int inner = c & 511;
                int h     = inner >> 6;
                int d     = inner & 63;
                int b0 = m_base >> 10, n0 = m_base & 1023;
                int m1 = m_base + 8;
                int b1 = m1 >> 10, n1 = m1 & 1023;
                size_t off0 = ((size_t)((b0 * NHEADS + h) * SEQ + n0)) * DHEAD + d;
                size_t off1 = ((size_t)((b1 * NHEADS + h) * SEQ + n1)) * DHEAD + d;
                if (which == 0) {
                    v0.x *= sc; v0.y *= sc; v1.x *= sc; v1.y *= sc;
                    *(uint32_t*)&g_q16hi[off0] = pack_h2(v0.x, v0.y);
                    *(uint32_t*)&g_q16lo[off0] = pack_h2_lo(v0.x, v0.y);
                    *(uint32_t*)&g_q16hi[off1] = pack_h2(v1.x, v1.y);
                    *(uint32_t*)&g_q16lo[off1] = pack_h2_lo(v1.x, v1.y);
                } else if (which == 1) {
                    *(uint32_t*)&g_k16[off0] = pack_h2(v0.x, v0.y);
                    *(uint32_t*)&g_k16[off1] = pack_h2(v1.x, v1.y);
                } else {
                    *(uint32_t*)&g_v16[off0] = pack_h2(v0.x, v0.y);
                    *(uint32_t*)&g_v16[off1] = pack_h2(v1.x, v1.y);
                }
            }
        }
    }
}

// ============================================================================
// Flash attention fp16 (R11): q-block 128, 4 warps x 32 q-rows, K-tiles 64.
// QK: Q split (2 MMA), K single. PV: P single, V single. EX2 softmax.
// Epilogue: fp16 hi/lo split attention output (feeds fp16 out-GEMM).
// ============================================================================
#define KST   72
#define ABUF  9216                 /* 64*KST*2 bytes */
#define ASTAGE (2*ABUF)            /* K, V */

__global__ __launch_bounds__(128, 2) void attn_hmma_kernel()
{
    extern __shared__ char smem[];
    const uint32_t uS = smem_u32(smem);

    const int tx   = threadIdx.x;
    const int lane = tx & 31;
    const int wq   = tx >> 5;
    const int bh   = blockIdx.y;
    const int q0   = blockIdx.x * 128;
    const size_t base = (size_t)bh * SEQ * DHEAD;

    // ---- stage Q (128 rows, hi+lo fp16) across the 4 ABUF regions ----
#pragma unroll
    for (int t = 0; t < 8; t++) {
        int id = tx + t * 128;
        int r  = id >> 3, c8 = (id & 7) << 3;
        uint32_t hb = (r < 64) ? 0u : (uint32_t)ABUF;
        uint32_t so = (uint32_t)((r & 63) * KST + c8) * 2;
        *(uint4*)(smem + hb + so)          = *(const uint4*)&g_q16hi[base + (size_t)(q0 + r) * DHEAD + c8];
        *(uint4*)(smem + 2*ABUF + hb + so) = *(const uint4*)&g_q16lo[base + (size_t)(q0 + r) * DHEAD + c8];
    }
    __syncthreads();

    const int a_row  = lane & 15;
    const int a_half = lane >> 4;
    uint32_t qh[2][4][4], ql[2][4][4];
#pragma unroll
    for (int mf = 0; mf < 2; mf++) {
        int gr = wq * 32 + mf * 16 + a_row;
        uint32_t hb = (gr < 64) ? 0u : (uint32_t)ABUF;
#pragma unroll
        for (int ks = 0; ks < 4; ks++) {
            uint32_t boff = (uint32_t)((gr & 63) * KST + ks * 16) * 2 + a_half * 16;
            ldm_x4(qh[mf][ks], uS + hb + boff);
            ldm_x4(ql[mf][ks], uS + 2*ABUF + hb + boff);
        }
    }
    __syncthreads();

    const int cr = tx >> 1;
    const int cc = (tx & 1) << 5;
    auto issue = [&](int kt, int s) {
        uint32_t sb = uS + s * ASTAGE;
#pragma unroll
        for (int t = 0; t < 4; t++) {
            int c8 = cc + t * 8;
            uint32_t so = (uint32_t)(cr * KST + c8) * 2;
            size_t g = base + (size_t)(kt * 64 + cr) * DHEAD + c8;
            cp16(sb + so,          g_k16 + g);
            cp16(sb + ABUF + so,   g_v16 + g);
        }
        cp_commit();
    };

    float oacc[2][8][4];
#pragma unroll
    for (int mf = 0; mf < 2; mf++)
#pragma unroll
        for (int i = 0; i < 8; i++)
#pragma unroll
            for (int j = 0; j < 4; j++) oacc[mf][i][j] = 0.f;
    float mrow[4] = {-INFINITY, -INFINITY, -INFINITY, -INFINITY};
    float lrow[4] = {0.f, 0.f, 0.f, 0.f};

    const int b_row  = (lane & 7) + ((lane >> 4) << 3);
    const int b_half = (lane >> 3) & 1;
    const int v_mat  = lane >> 3;
    const int v_row  = lane & 7;
    const int ra     = lane >> 2;
    const int c_in   = 2 * (lane & 3);

    issue(0, 0);
    for (int kt = 0; kt < 16; kt++) {
        if (kt + 1 < 16) { issue(kt + 1, (kt + 1) & 1); cp_wait<1>(); }
        else             { cp_wait<0>(); }
        __syncthreads();

        const uint32_t sb = uS + (kt & 1) * ASTAGE;
        const uint32_t uKh = sb, uVh = sb + ABUF;

        // ---- S = Q K^T ----
        float sacc[2][8][4];
#pragma unroll
        for (int mf = 0; mf < 2; mf++)
#pragma unroll
            for (int i = 0; i < 8; i++)
#pragma unroll
                for (int j = 0; j < 4; j++) sacc[mf][i][j] = 0.f;
#pragma unroll
        for (int nf2 = 0; nf2 < 4; nf2++) {
#pragma unroll
            for (int ks = 0; ks < 4; ks++) {
                uint32_t kh[4];
                uint32_t boff = (uint32_t)((nf2 * 16 + b_row) * KST + ks * 16) * 2 + b_half * 16;
                ldm_x4(kh, uKh + boff);
#pragma unroll
                for (int mf = 0; mf < 2; mf++) {
                    mma_fp16(sacc[mf][2*nf2],   qh[mf][ks], kh);
                    mma_fp16(sacc[mf][2*nf2+1], qh[mf][ks], kh + 2);
                    mma_fp16(sacc[mf][2*nf2],   ql[mf][ks], kh);
                    mma_fp16(sacc[mf][2*nf2+1], ql[mf][ks], kh + 2);
                }
            }
        }

        // ---- diagonal mask ----
        if ((kt >> 1) == blockIdx.x) {
#pragma unroll
            for (int mf = 0; mf < 2; mf++) {
                int row_a = q0 + wq * 32 + mf * 16 + ra;
                int row_b = row_a + 8;
#pragma unroll
                for (int nf = 0; nf < 8; nf++) {
                    int col = kt * 64 + nf * 8 + c_in;
                    if (col     == row_a) sacc[mf][nf][0] = -INFINITY;
                    if (col + 1 == row_a) sacc[mf][nf][1] = -INFINITY;
                    if (col     == row_b) sacc[mf][nf][2] = -INFINITY;
                    if (col + 1 == row_b) sacc[mf][nf][3] = -INFINITY;
                }
            }
        }

        // ---- online softmax (base-2, MUFU EX2) ----
        float mt[4] = {-INFINITY, -INFINITY, -INFINITY, -INFINITY};
#pragma unroll
        for (int mf = 0; mf < 2; mf++)
#pragma unroll
            for (int nf = 0; nf < 8; nf++) {
                mt[2*mf]   = fmaxf(mt[2*mf],   fmaxf(sacc[mf][nf][0], sacc[mf][nf][1]));
                mt[2*mf+1] = fmaxf(mt[2*mf+1], fmaxf(sacc[mf][nf][2], sacc[mf][nf][3]));
            }
#pragma unroll
        for (int i = 0; i < 4; i++) {
            mt[i] = fmaxf(mt[i], __shfl_xor_sync(0xffffffffu, mt[i], 1));
            mt[i] = fmaxf(mt[i], __shfl_xor_sync(0xffffffffu, mt[i], 2));
        }

        float mn[4], ls[4] = {0.f, 0.f, 0.f, 0.f};
#pragma unroll
        for (int i = 0; i < 4; i++) mn[i] = fmaxf(mrow[i], mt[i]);
#pragma unroll
        for (int mf = 0; mf < 2; mf++)
#pragma unroll
            for (int nf = 0; nf < 8; nf++) {
                float p0 = ex2(sacc[mf][nf][0] - mn[2*mf]);
                float p1 = ex2(sacc[mf][nf][1] - mn[2*mf]);
                float p2 = ex2(sacc[mf][nf][2] - mn[2*mf+1]);
                float p3 = ex2(sacc[mf][nf][3] - mn[2*mf+1]);
                ls[2*mf] += p0 + p1; ls[2*mf+1] += p2 + p3;
                sacc[mf][nf][0] = p0; sacc[mf][nf][1] = p1;
                sacc[mf][nf][2] = p2; sacc[mf][nf][3] = p3;
            }
#pragma unroll
        for (int i = 0; i < 4; i++) {
            if (mn[i] > mrow[i]) {
                float cr_ = ex2(mrow[i] - mn[i]);
                lrow[i] *= cr_;
                int mf = i >> 1, j0 = (i & 1) * 2;
#pragma unroll
                for (int nf = 0; nf < 8; nf++) {
                    oacc[mf][nf][j0]     *= cr_;
                    oacc[mf][nf][j0 + 1] *= cr_;
                }
                mrow[i] = mn[i];
            }
            lrow[i] += ls[i];
        }

        // ---- O += P V ----
#pragma unroll
        for (int kb = 0; kb < 4; kb++) {
            uint32_t pa[2][4];
#pragma unroll
            for (int mf = 0; mf < 2; mf++) {
                pa[mf][0] = pack_h2(sacc[mf][2*kb][0],   sacc[mf][2*kb][1]);
                pa[mf][1] = pack_h2(sacc[mf][2*kb][2],   sacc[mf][2*kb][3]);
                pa[mf][2] = pack_h2(sacc[mf][2*kb+1][0], sacc[mf][2*kb+1][1]);
                pa[mf][3] = pack_h2(sacc[mf][2*kb+1][2], sacc[mf][2*kb+1][3]);
            }
#pragma unroll
            for (int nf2 = 0; nf2 < 4; nf2++) {
                uint32_t boff = (uint32_t)((kb * 16 + (v_mat & 1) * 8 + v_row) * KST
                                           + nf2 * 16 + (v_mat >> 1) * 8) * 2;
                uint32_t vh[4];
                ldm_x4t(vh, uVh + boff);
#pragma unroll
                for (int mf = 0; mf < 2; mf++) {
                    mma_fp16(oacc[mf][2*nf2],   pa[mf], vh);
                    mma_fp16(oacc[mf][2*nf2+1], pa[mf], vh + 2);
                }
            }
        }
        __syncthreads();
    }

    // ---- finalize: fp16 hi/lo split output for the out-projection ----
#pragma unroll
    for (int i = 0; i < 4; i++) {
        lrow[i] += __shfl_xor_sync(0xffffffffu, lrow[i], 1);
        lrow[i] += __shfl_xor_sync(0xffffffffu, lrow[i], 2);
    }

    const int b_ = bh >> 3, h = bh & 7;
#pragma unroll
    for (int mf = 0; mf < 2; mf++) {
        int row_a = q0 + wq * 32 + mf * 16 + ra;
        float inv0 = 1.f / lrow[2*mf], inv1 = 1.f / lrow[2*mf+1];
#pragma unroll
        for (int nf = 0; nf < 8; nf++) {
            int col = h * DHEAD + nf * 8 + c_in;
            size_t o0 = (size_t)(b_ * SEQ + row_a) * INNER + col;
            size_t o1 = (size_t)(b_ * SEQ + row_a + 8) * INNER + col;
            float a0 = oacc[mf][nf][0] * inv0, a1 = oacc[mf][nf][1] * inv0;
            float a2 = oacc[mf][nf][2] * inv1, a3 = oacc[mf][nf][3] * inv1;
            *(uint32_t*)&g_ao16hi[o0] = pack_h2(a0, a1);
            *(uint32_t*)&g_ao16lo[o0] = pack_h2_lo(a0, a1);
            *(uint32_t*)&g_ao16hi[o1] = pack_h2(a2, a3);
            *(uint32_t*)&g_ao16lo[o1] = pack_h2_lo(a2, a3);
        }
    }
}

// ============================================================================
extern "C" void kernel_launch(void* const* d_in, const int* in_sizes, int n_in,
                              void* d_out, int out_size)
{
    const float* x    = nullptr;
    const float* wqkv = nullptr;
    const float* wout = nullptr;
    const float* temp = nullptr;
    for (int i = 0; i < n_in; i++) {
        switch (in_sizes[i]) {
            case 4194304: x    = (const float*)d_in[i]; break;
            case 786432:  wqkv = (const float*)d_in[i]; break;
            case 262144:  wout = (const float*)d_in[i]; break;
            case 1:       temp = (const float*)d_in[i]; break;
            default: break;
        }
    }
    float* out = (float*)d_out;

    static int attr_done = 0;
    if (!attr_done) {
        cudaFuncSetAttribute(gemm_hmma_kernel,
                             cudaFuncAttributeMaxDynamicSharedMemorySize, 2 * GSTAGE);
        cudaFuncSetAttribute(attn_hmma_kernel,
                             cudaFuncAttributeMaxDynamicSharedMemorySize, 2 * ASTAGE);
        attr_done = 1;
    }

    __half *w16q, *w16o, *x16hi, *x16lo, *ao16hi, *ao16lo;
    cudaGetSymbolAddress((void**)&w16q,   g_w16qkv);
    cudaGetSymbolAddress((void**)&w16o,   g_w16out);
    cudaGetSymbolAddress((void**)&x16hi,  g_x16hi);
    cudaGetSymbolAddress((void**)&x16lo,  g_x16lo);
    cudaGetSymbolAddress((void**)&ao16hi, g_ao16hi);
    cudaGetSymbolAddress((void**)&ao16lo, g_ao16lo);

    xsplit_kernel<<<M_TOT * DIM / (256 * 4), 256>>>(x);
    wconv_kernel<<<dim3(48, 16), dim3(32, 32)>>>(wqkv, w16q, 3 * INNER);
    wconv_kernel<<<dim3(16, 16), dim3(32, 32)>>>(wout, w16o, INNER);

    gemm_hmma_kernel<<<dim3(12, 64), 256, 2 * GSTAGE>>>(x16hi, x16lo, w16q,
                                                        nullptr, temp, 0);
    attn_hmma_kernel<<<dim3(8, 64), 128, 2 * ASTAGE>>>();
    gemm_hmma_kernel<<<dim3(4, 64), 256, 2 * GSTAGE>>>(ao16hi, ao16lo, w16o,
                                                       out, temp, 1);
    (void)out_size;
}

// round 13
// speedup vs baseline: 2.0953x; 1.1122x over previous
#include <cuda_runtime.h>
#include <cuda_bf16.h>
#include <cuda_fp16.h>
#include <math.h>
#include <stdint.h>

#define NB      8
#define SEQ     1024
#define DIM     512
#define NHEADS  8
#define DHEAD   64
#define INNER   512
#define M_TOT   (NB*SEQ)        /* 8192 */
#define BH      (NB*NHEADS)     /* 64 */

// ---- scratch (allocation-free: __device__ globals), fp16 ----
__device__ __half g_x16hi [(size_t)M_TOT*DIM];     // split x
__device__ __half g_x16lo [(size_t)M_TOT*DIM];
__device__ __half g_ao16  [(size_t)M_TOT*INNER];   // single-fp16 attn output
// attention operands, [bh][n][d]; q has exp(temperature)*log2(e) folded in
__device__ __half g_q16[(size_t)BH*SEQ*DHEAD];
__device__ __half g_k16[(size_t)BH*SEQ*DHEAD];
__device__ __half g_v16[(size_t)BH*SEQ*DHEAD];
// pre-transposed single-fp16 weights: [n][k]
__device__ __half g_w16qkv[(size_t)3*INNER*DIM];
__device__ __half g_w16out[(size_t)DIM*INNER];

// ========================== helpers ===========================
__device__ __forceinline__ uint32_t smem_u32(const void* p) {
    uint32_t a;
    asm("{ .reg .u64 t; cvta.to.shared.u64 t, %1; cvt.u32.u64 %0, t; }" : "=r"(a) : "l"(p));
    return a;
}
__device__ __forceinline__ void ldm_x4(uint32_t* f, uint32_t addr) {
    asm volatile("ldmatrix.sync.aligned.m8n8.x4.shared.b16 {%0,%1,%2,%3}, [%4];"
                 : "=r"(f[0]), "=r"(f[1]), "=r"(f[2]), "=r"(f[3]) : "r"(addr));
}
__device__ __forceinline__ void ldm_x4t(uint32_t* f, uint32_t addr) {
    asm volatile("ldmatrix.sync.aligned.m8n8.x4.trans.shared.b16 {%0,%1,%2,%3}, [%4];"
                 : "=r"(f[0]), "=r"(f[1]), "=r"(f[2]), "=r"(f[3]) : "r"(addr));
}
__device__ __forceinline__ void mma_fp16(float* d, const uint32_t* a, const uint32_t* b) {
    asm("mma.sync.aligned.m16n8k16.row.col.f32.f16.f16.f32 "
        "{%0,%1,%2,%3}, {%4,%5,%6,%7}, {%8,%9}, {%0,%1,%2,%3};"
        : "+f"(d[0]), "+f"(d[1]), "+f"(d[2]), "+f"(d[3])
        : "r"(a[0]), "r"(a[1]), "r"(a[2]), "r"(a[3]), "r"(b[0]), "r"(b[1]));
}
__device__ __forceinline__ uint32_t pack_h2(float x, float y) {
    __half2 h = __floats2half2_rn(x, y);
    return *(uint32_t*)&h;
}
__device__ __forceinline__ uint32_t pack_h2_lo(float x, float y) {
    float rx = x - __half2float(__float2half_rn(x));
    float ry = y - __half2float(__float2half_rn(y));
    __half2 h = __floats2half2_rn(rx, ry);
    return *(uint32_t*)&h;
}
// hardware EX2 (MUFU); ex2(-inf)=0
__device__ __forceinline__ float ex2(float x) {
    float y;
    asm("ex2.approx.f32 %0, %1;" : "=f"(y) : "f"(x));
    return y;
}
__device__ __forceinline__ void cp16(uint32_t sdst, const void* gsrc) {
    asm volatile("cp.async.cg.shared.global [%0], [%1], 16;" :: "r"(sdst), "l"(gsrc));
}
__device__ __forceinline__ void cp_commit() { asm volatile("cp.async.commit_group;"); }
template <int N> __device__ __forceinline__ void cp_wait() {
    asm volatile("cp.async.wait_group %0;" :: "n"(N));
}

// ============================================================================
// Prep: split x fp32 -> fp16 hi/lo
// ============================================================================
__global__ __launch_bounds__(256) void xsplit_kernel(const float* __restrict__ X)
{
    size_t i = ((size_t)blockIdx.x * 256 + threadIdx.x) * 4;
    float4 v = *(const float4*)&X[i];
    *(uint2*)&g_x16hi[i] = make_uint2(pack_h2(v.x, v.y), pack_h2(v.z, v.w));
    *(uint2*)&g_x16lo[i] = make_uint2(pack_h2_lo(v.x, v.y), pack_h2_lo(v.z, v.w));
}

// ============================================================================
// Prep: transpose [512][N] fp32 -> [N][512] single fp16
// ============================================================================
__global__ void wconv_kernel(const float* __restrict__ W,
                             __half* __restrict__ out, int N)
{
    __shared__ float t[32][33];
    int n = blockIdx.x * 32 + threadIdx.x;
    int k = blockIdx.y * 32 + threadIdx.y;
    t[threadIdx.y][threadIdx.x] = W[(size_t)k * N + n];
    __syncthreads();
    int n2 = blockIdx.x * 32 + threadIdx.y;
    int k2 = blockIdx.y * 32 + threadIdx.x;
    out[(size_t)n2 * DIM + k2] = __float2half_rn(t[threadIdx.x][threadIdx.y]);
}

// ============================================================================
// HMMA GEMM fp16: 256 thr, 8 warps (4x2), warp 32x64, BK=32.
// asplit=1: split-fp16 activations (2-MMA); asplit=0: single-fp16 (1-MMA).
// mode 0: epilogue emits fp16 q(scaled)/k/v; mode 1: fp32 C.
// ============================================================================
#define BK   32
#define PAD  40
#define GST  10240
#define GSTAGE (3*GST)             /* Ahi, Alo, B */

__global__ __launch_bounds__(256, 2) void gemm_hmma_kernel(
    const __half* __restrict__ Ahi,
    const __half* __restrict__ Alo,
    const __half* __restrict__ B,
    float* __restrict__ C, const float* __restrict__ temp, int mode, int asplit)
{
    extern __shared__ char smem[];
    const uint32_t uS = smem_u32(smem);

    const int tx   = threadIdx.x;
    const int lane = tx & 31;
    const int wid  = tx >> 5;
    const int wm   = wid >> 1;
    const int wn   = wid & 1;
    const int row0 = blockIdx.y * 128;
    const int col0 = blockIdx.x * 128;

    const int cr = tx >> 2;
    const int cc = (tx & 3) << 3;
    auto issue = [&](int kc, int s) {
        uint32_t sb = uS + s * GSTAGE;
#pragma unroll
        for (int t = 0; t < 2; t++) {
            int r = cr + t * 64;
            uint32_t so = (uint32_t)(r * PAD + cc) * 2;
            size_t  ga = (size_t)(row0 + r) * DIM + kc + cc;
            size_t  gb = (size_t)(col0 + r) * DIM + kc + cc;
            cp16(sb + so,           Ahi + ga);
            if (asplit) cp16(sb + GST + so, Alo + ga);
            cp16(sb + 2*GST + so,   B   + gb);
        }
        cp_commit();
    };

    float acc[2][8][4];
#pragma unroll
    for (int i = 0; i < 2; i++)
#pragma unroll
        for (int j = 0; j < 8; j++)
#pragma unroll
            for (int t = 0; t < 4; t++) acc[i][j][t] = 0.f;

    const int a_row  = lane & 15;
    const int a_half = lane >> 4;
    const int b_row  = (lane & 7) + ((lane >> 4) << 3);
    const int b_half = (lane >> 3) & 1;

    issue(0, 0);
    const int KITER = DIM / BK;        // 16
    for (int kc = 0; kc < KITER; kc++) {
        if (kc + 1 < KITER) { issue((kc + 1) * BK, (kc + 1) & 1); cp_wait<1>(); }
        else                { cp_wait<0>(); }
        __syncthreads();

        const uint32_t sb = uS + (kc & 1) * GSTAGE;
        const uint32_t uAhi = sb, uAlo = sb + GST, uB = sb + 2*GST;
#pragma unroll
        for (int kk = 0; kk < 2; kk++) {
            uint32_t afh[2][4], afl[2][4];
#pragma unroll
            for (int mf = 0; mf < 2; mf++) {
                uint32_t boff = (uint32_t)((wm * 32 + mf * 16 + a_row) * PAD + kk * 16) * 2
                              + a_half * 16;
                ldm_x4(afh[mf], uAhi + boff);
                if (asplit) ldm_x4(afl[mf], uAlo + boff);
            }
            uint32_t bf[8][2];
#pragma unroll
            for (int nf2 = 0; nf2 < 4; nf2++) {
                uint32_t boff = (uint32_t)((wn * 64 + nf2 * 16 + b_row) * PAD + kk * 16) * 2
                              + b_half * 16;
                uint32_t th[4];
                ldm_x4(th, uB + boff);
                bf[nf2*2][0] = th[0]; bf[nf2*2][1] = th[1];
                bf[nf2*2+1][0] = th[2]; bf[nf2*2+1][1] = th[3];
            }
#pragma unroll
            for (int mf = 0; mf < 2; mf++)
#pragma unroll
                for (int nf = 0; nf < 8; nf++)
                    mma_fp16(acc[mf][nf], afh[mf], bf[nf]);
            if (asplit) {
#pragma unroll
                for (int mf = 0; mf < 2; mf++)
#pragma unroll
                    for (int nf = 0; nf < 8; nf++)
                        mma_fp16(acc[mf][nf], afl[mf], bf[nf]);
            }
        }
        __syncthreads();
    }

    // q pre-scale: exp(temperature)*log2(e) -> attention works in log2 domain
    const float sc = (mode == 0) ? __expf(*temp) * 1.44269504f : 1.f;
#pragma unroll
    for (int mf = 0; mf < 2; mf++) {
        int m_base = row0 + wm * 32 + mf * 16 + (lane >> 2);
#pragma unroll
        for (int nf = 0; nf < 8; nf++) {
            int c = col0 + wn * 64 + nf * 8 + 2 * (lane & 3);
            float2 v0 = make_float2(acc[mf][nf][0], acc[mf][nf][1]);
            float2 v1 = make_float2(acc[mf][nf][2], acc[mf][nf][3]);
            if (mode == 1) {
                *(float2*)&C[(size_t)m_base * DIM + c]       = v0;
                *(float2*)&C[(size_t)(m_base + 8) * DIM + c] = v1;
            } else {
                int which = c >> 9;
                int inner = c & 511;
                int h     = inner >> 6;
                int d     = inner & 63;
                int b0 = m_base >> 10, n0 = m_base & 1023;
                int m1 = m_base + 8;
                int b1 = m1 >> 10, n1 = m1 & 1023;
                size_t off0 = ((size_t)((b0 * NHEADS + h) * SEQ + n0)) * DHEAD + d;
                size_t off1 = ((size_t)((b1 * NHEADS + h) * SEQ + n1)) * DHEAD + d;
                __half* dst;
                if (which == 0) {
                    v0.x *= sc; v0.y *= sc; v1.x *= sc; v1.y *= sc;
                    dst = g_q16;
                } else if (which == 1) dst = g_k16;
                else                   dst = g_v16;
                *(uint32_t*)&dst[off0] = pack_h2(v0.x, v0.y);
                *(uint32_t*)&dst[off1] = pack_h2(v1.x, v1.y);
            }
        }
    }
}

// ============================================================================
// Flash attention fp16: q-block 128, 4 warps x 32 q-rows, K-tiles 64.
// QK: single-Q x single-K (1 MMA). PV: single P x single V (1 MMA).
// 2-stage cp.async (K,V), EX2 softmax. Output: single fp16 ao.
// ============================================================================
#define KST   72
#define ABUF  9216                 /* 64*KST*2 bytes */
#define ASTAGE (2*ABUF)            /* K, V */

__global__ __launch_bounds__(128, 2) void attn_hmma_kernel()
{
    extern __shared__ char smem[];
    const uint32_t uS = smem_u32(smem);

    const int tx   = threadIdx.x;
    const int lane = tx & 31;
    const int wq   = tx >> 5;
    const int bh   = blockIdx.y;
    const int q0   = blockIdx.x * 128;
    const size_t base = (size_t)bh * SEQ * DHEAD;

    // ---- stage Q (128 rows fp16) into the two stage-0 buffers ----
#pragma unroll
    for (int t = 0; t < 4; t++) {
        int id = tx + t * 128;
        int r  = id >> 2, c8 = (id & 3) << 4;   // 128 rows x 2 chunks of 16B... wait
        // 128 rows * 128B = 16KB; 512 iterations of 16B chunks -> id 0..511
        // r = id >> 2 (0..127), chunk = (id & 3) * 16 bytes = (id&3)*8 halves
        int c8h = (id & 3) << 4;                // half-index? 4 chunks x 8 halves=32... 
        (void)c8; (void)c8h;
    }
    // (redo cleanly below)
#pragma unroll
    for (int t = 0; t < 8; t++) {
        int id = tx + t * 128;                 // 0..1023
        int r  = id >> 3, c8 = (id & 7) << 3;  // 128 rows x 8 chunks of 8 halves
        uint32_t hb = (r < 64) ? 0u : (uint32_t)ABUF;
        uint32_t so = (uint32_t)((r & 63) * KST + c8) * 2;
        *(uint4*)(smem + hb + so) = *(const uint4*)&g_q16[base + (size_t)(q0 + r) * DHEAD + c8];
    }
    __syncthreads();

    const int a_row  = lane & 15;
    const int a_half = lane >> 4;
    uint32_t qh[2][4][4];
#pragma unroll
    for (int mf = 0; mf < 2; mf++) {
        int gr = wq * 32 + mf * 16 + a_row;
        uint32_t hb = (gr < 64) ? 0u : (uint32_t)ABUF;
#pragma unroll
        for (int ks = 0; ks < 4; ks++) {
            uint32_t boff = (uint32_t)((gr & 63) * KST + ks * 16) * 2 + a_half * 16;
            ldm_x4(qh[mf][ks], uS + hb + boff);
        }
    }
    __syncthreads();

    const int cr = tx >> 1;
    const int cc = (tx & 1) << 5;
    auto issue = [&](int kt, int s) {
        uint32_t sb = uS + s * ASTAGE;
#pragma unroll
        for (int t = 0; t < 4; t++) {
            int c8 = cc + t * 8;
            uint32_t so = (uint32_t)(cr * KST + c8) * 2;
            size_t g = base + (size_t)(kt * 64 + cr) * DHEAD + c8;
            cp16(sb + so,          g_k16 + g);
            cp16(sb + ABUF + so,   g_v16 + g);
        }
        cp_commit();
    };

    float oacc[2][8][4];
#pragma unroll
    for (int mf = 0; mf < 2; mf++)
#pragma unroll
        for (int i = 0; i < 8; i++)
#pragma unroll
            for (int j = 0; j < 4; j++) oacc[mf][i][j] = 0.f;
    float mrow[4] = {-INFINITY, -INFINITY, -INFINITY, -INFINITY};
    float lrow[4] = {0.f, 0.f, 0.f, 0.f};

    const int b_row  = (lane & 7) + ((lane >> 4) << 3);
    const int b_half = (lane >> 3) & 1;
    const int v_mat  = lane >> 3;
    const int v_row  = lane & 7;
    const int ra     = lane >> 2;
    const int c_in   = 2 * (lane & 3);

    issue(0, 0);
    for (int kt = 0; kt < 16; kt++) {
        if (kt + 1 < 16) { issue(kt + 1, (kt + 1) & 1); cp_wait<1>(); }
        else             { cp_wait<0>(); }
        __syncthreads();

        const uint32_t sb = uS + (kt & 1) * ASTAGE;
        const uint32_t uKh = sb, uVh = sb + ABUF;

        // ---- S = Q K^T (single-Q, 1 MMA per frag pair) ----
        float sacc[2][8][4];
#pragma unroll
        for (int mf = 0; mf < 2; mf++)
#pragma unroll
            for (int i = 0; i < 8; i++)
#pragma unroll
                for (int j = 0; j < 4; j++) sacc[mf][i][j] = 0.f;
#pragma unroll
        for (int nf2 = 0; nf2 < 4; nf2++) {
#pragma unroll
            for (int ks = 0; ks < 4; ks++) {
                uint32_t kh[4];
                uint32_t boff = (uint32_t)((nf2 * 16 + b_row) * KST + ks * 16) * 2 + b_half * 16;
                ldm_x4(kh, uKh + boff);
#pragma unroll
                for (int mf = 0; mf < 2; mf++) {
                    mma_fp16(sacc[mf][2*nf2],   qh[mf][ks], kh);
                    mma_fp16(sacc[mf][2*nf2+1], qh[mf][ks], kh + 2);
                }
            }
        }

        // ---- diagonal mask ----
        if ((kt >> 1) == blockIdx.x) {
#pragma unroll
            for (int mf = 0; mf < 2; mf++) {
                int row_a = q0 + wq * 32 + mf * 16 + ra;
                int row_b = row_a + 8;
#pragma unroll
                for (int nf = 0; nf < 8; nf++) {
                    int col = kt * 64 + nf * 8 + c_in;
                    if (col     == row_a) sacc[mf][nf][0] = -INFINITY;
                    if (col + 1 == row_a) sacc[mf][nf][1] = -INFINITY;
                    if (col     == row_b) sacc[mf][nf][2] = -INFINITY;
                    if (col + 1 == row_b) sacc[mf][nf][3] = -INFINITY;
                }
            }
        }

        // ---- online softmax (base-2, MUFU EX2) ----
        float mt[4] = {-INFINITY, -INFINITY, -INFINITY, -INFINITY};
#pragma unroll
        for (int mf = 0; mf < 2; mf++)
#pragma unroll
            for (int nf = 0; nf < 8; nf++) {
                mt[2*mf]   = fmaxf(mt[2*mf],   fmaxf(sacc[mf][nf][0], sacc[mf][nf][1]));
                mt[2*mf+1] = fmaxf(mt[2*mf+1], fmaxf(sacc[mf][nf][2], sacc[mf][nf][3]));
            }
#pragma unroll
        for (int i = 0; i < 4; i++) {
            mt[i] = fmaxf(mt[i], __shfl_xor_sync(0xffffffffu, mt[i], 1));
            mt[i] = fmaxf(mt[i], __shfl_xor_sync(0xffffffffu, mt[i], 2));
        }

        float mn[4], ls[4] = {0.f, 0.f, 0.f, 0.f};
#pragma unroll
        for (int i = 0; i < 4; i++) mn[i] = fmaxf(mrow[i], mt[i]);
#pragma unroll
        for (int mf = 0; mf < 2; mf++)
#pragma unroll
            for (int nf = 0; nf < 8; nf++) {
                float p0 = ex2(sacc[mf][nf][0] - mn[2*mf]);
                float p1 = ex2(sacc[mf][nf][1] - mn[2*mf]);
                float p2 = ex2(sacc[mf][nf][2] - mn[2*mf+1]);
                float p3 = ex2(sacc[mf][nf][3] - mn[2*mf+1]);
                ls[2*mf] += p0 + p1; ls[2*mf+1] += p2 + p3;
                sacc[mf][nf][0] = p0; sacc[mf][nf][1] = p1;
                sacc[mf][nf][2] = p2; sacc[mf][nf][3] = p3;
            }
#pragma unroll
        for (int i = 0; i < 4; i++) {
            if (mn[i] > mrow[i]) {
                float cr_ = ex2(mrow[i] - mn[i]);
                lrow[i] *= cr_;
                int mf = i >> 1, j0 = (i & 1) * 2;
#pragma unroll
                for (int nf = 0; nf < 8; nf++) {
                    oacc[mf][nf][j0]     *= cr_;
                    oacc[mf][nf][j0 + 1] *= cr_;
                }
                mrow[i] = mn[i];
            }
            lrow[i] += ls[i];
        }

        // ---- O += P V ----
#pragma unroll
        for (int kb = 0; kb < 4; kb++) {
            uint32_t pa[2][4];
#pragma unroll
            for (int mf = 0; mf < 2; mf++) {
                pa[mf][0] = pack_h2(sacc[mf][2*kb][0],   sacc[mf][2*kb][1]);
                pa[mf][1] = pack_h2(sacc[mf][2*kb][2],   sacc[mf][2*kb][3]);
                pa[mf][2] = pack_h2(sacc[mf][2*kb+1][0], sacc[mf][2*kb+1][1]);
                pa[mf][3] = pack_h2(sacc[mf][2*kb+1][2], sacc[mf][2*kb+1][3]);
            }
#pragma unroll
            for (int nf2 = 0; nf2 < 4; nf2++) {
                uint32_t boff = (uint32_t)((kb * 16 + (v_mat & 1) * 8 + v_row) * KST
                                           + nf2 * 16 + (v_mat >> 1) * 8) * 2;
                uint32_t vh[4];
                ldm_x4t(vh, uVh + boff);
#pragma unroll
                for (int mf = 0; mf < 2; mf++) {
                    mma_fp16(oacc[mf][2*nf2],   pa[mf], vh);
                    mma_fp16(oacc[mf][2*nf2+1], pa[mf], vh + 2);
                }
            }
        }
        __syncthreads();
    }

    // ---- finalize: single fp16 ao ----
#pragma unroll
    for (int i = 0; i < 4; i++) {
        lrow[i] += __shfl_xor_sync(0xffffffffu, lrow[i], 1);
        lrow[i] += __shfl_xor_sync(0xffffffffu, lrow[i], 2);
    }

    const int b_ = bh >> 3, h = bh & 7;
#pragma unroll
    for (int mf = 0; mf < 2; mf++) {
        int row_a = q0 + wq * 32 + mf * 16 + ra;
        float inv0 = 1.f / lrow[2*mf], inv1 = 1.f / lrow[2*mf+1];
#pragma unroll
        for (int nf = 0; nf < 8; nf++) {
            int col = h * DHEAD + nf * 8 + c_in;
            size_t o0 = (size_t)(b_ * SEQ + row_a) * INNER + col;
            size_t o1 = (size_t)(b_ * SEQ + row_a + 8) * INNER + col;
            *(uint32_t*)&g_ao16[o0] = pack_h2(oacc[mf][nf][0] * inv0, oacc[mf][nf][1] * inv0);
            *(uint32_t*)&g_ao16[o1] = pack_h2(oacc[mf][nf][2] * inv1, oacc[mf][nf][3] * inv1);
        }
    }
}

// ============================================================================
extern "C" void kernel_launch(void* const* d_in, const int* in_sizes, int n_in,
                              void* d_out, int out_size)
{
    const float* x    = nullptr;
    const float* wqkv = nullptr;
    const float* wout = nullptr;
    const float* temp = nullptr;
    for (int i = 0; i < n_in; i++) {
        switch (in_sizes[i]) {
            case 4194304: x    = (const float*)d_in[i]; break;
            case 786432:  wqkv = (const float*)d_in[i]; break;
            case 262144:  wout = (const float*)d_in[i]; break;
            case 1:       temp = (const float*)d_in[i]; break;
            default: break;
        }
    }
    float* out = (float*)d_out;

    static int attr_done = 0;
    if (!attr_done) {
        cudaFuncSetAttribute(gemm_hmma_kernel,
                             cudaFuncAttributeMaxDynamicSharedMemorySize, 2 * GSTAGE);
        cudaFuncSetAttribute(attn_hmma_kernel,
                             cudaFuncAttributeMaxDynamicSharedMemorySize, 2 * ASTAGE);
        attr_done = 1;
    }

    __half *w16q, *w16o, *x16hi, *x16lo, *ao16;
    cudaGetSymbolAddress((void**)&w16q,  g_w16qkv);
    cudaGetSymbolAddress((void**)&w16o,  g_w16out);
    cudaGetSymbolAddress((void**)&x16hi, g_x16hi);
    cudaGetSymbolAddress((void**)&x16lo, g_x16lo);
    cudaGetSymbolAddress((void**)&ao16,  g_ao16);

    xsplit_kernel<<<M_TOT * DIM / (256 * 4), 256>>>(x);
    wconv_kernel<<<dim3(48, 16), dim3(32, 32)>>>(wqkv, w16q, 3 * INNER);
    wconv_kernel<<<dim3(16, 16), dim3(32, 32)>>>(wout, w16o, INNER);

    gemm_hmma_kernel<<<dim3(12, 64), 256, 2 * GSTAGE>>>(x16hi, x16lo, w16q,
                                                        nullptr, temp, 0, 1);
    attn_hmma_kernel<<<dim3(8, 64), 128, 2 * ASTAGE>>>();
    gemm_hmma_kernel<<<dim3(4, 64), 256, 2 * GSTAGE>>>(ao16, nullptr, w16o,
                                                       out, temp, 1, 0);
    (void)out_size;
}

// round 14
// speedup vs baseline: 2.5373x; 1.2109x over previous
#include <cuda_runtime.h>
#include <cuda_bf16.h>
#include <cuda_fp16.h>
#include <math.h>
#include <stdint.h>

#define NB      8
#define SEQ     1024
#define DIM     512
#define NHEADS  8
#define DHEAD   64
#define INNER   512
#define M_TOT   (NB*SEQ)        /* 8192 */
#define BH      (NB*NHEADS)     /* 64 */

// ---- scratch (allocation-free: __device__ globals), single fp16 ----
__device__ __half g_x16 [(size_t)M_TOT*DIM];
__device__ __half g_ao16[(size_t)M_TOT*INNER];
// attention operands, [bh][n][d]; q has exp(temperature)*log2(e) folded in
__device__ __half g_q16[(size_t)BH*SEQ*DHEAD];
__device__ __half g_k16[(size_t)BH*SEQ*DHEAD];
__device__ __half g_v16[(size_t)BH*SEQ*DHEAD];
// pre-transposed single-fp16 weights: [n][k]
__device__ __half g_w16qkv[(size_t)3*INNER*DIM];
__device__ __half g_w16out[(size_t)DIM*INNER];

// ========================== helpers ===========================
__device__ __forceinline__ uint32_t smem_u32(const void* p) {
    uint32_t a;
    asm("{ .reg .u64 t; cvta.to.shared.u64 t, %1; cvt.u32.u64 %0, t; }" : "=r"(a) : "l"(p));
    return a;
}
__device__ __forceinline__ void ldm_x4(uint32_t* f, uint32_t addr) {
    asm volatile("ldmatrix.sync.aligned.m8n8.x4.shared.b16 {%0,%1,%2,%3}, [%4];"
                 : "=r"(f[0]), "=r"(f[1]), "=r"(f[2]), "=r"(f[3]) : "r"(addr));
}
__device__ __forceinline__ void ldm_x4t(uint32_t* f, uint32_t addr) {
    asm volatile("ldmatrix.sync.aligned.m8n8.x4.trans.shared.b16 {%0,%1,%2,%3}, [%4];"
                 : "=r"(f[0]), "=r"(f[1]), "=r"(f[2]), "=r"(f[3]) : "r"(addr));
}
__device__ __forceinline__ void mma_fp16(float* d, const uint32_t* a, const uint32_t* b) {
    asm("mma.sync.aligned.m16n8k16.row.col.f32.f16.f16.f32 "
        "{%0,%1,%2,%3}, {%4,%5,%6,%7}, {%8,%9}, {%0,%1,%2,%3};"
        : "+f"(d[0]), "+f"(d[1]), "+f"(d[2]), "+f"(d[3])
        : "r"(a[0]), "r"(a[1]), "r"(a[2]), "r"(a[3]), "r"(b[0]), "r"(b[1]));
}
__device__ __forceinline__ uint32_t pack_h2(float x, float y) {
    __half2 h = __floats2half2_rn(x, y);
    return *(uint32_t*)&h;
}
// hardware EX2 (MUFU); ex2(-inf)=0
__device__ __forceinline__ float ex2(float x) {
    float y;
    asm("ex2.approx.f32 %0, %1;" : "=f"(y) : "f"(x));
    return y;
}
__device__ __forceinline__ void cp16(uint32_t sdst, const void* gsrc) {
    asm volatile("cp.async.cg.shared.global [%0], [%1], 16;" :: "r"(sdst), "l"(gsrc));
}
__device__ __forceinline__ void cp_commit() { asm volatile("cp.async.commit_group;"); }
template <int N> __device__ __forceinline__ void cp_wait() {
    asm volatile("cp.async.wait_group %0;" :: "n"(N));
}

// ============================================================================
// Prep: x fp32 -> single fp16
// ============================================================================
__global__ __launch_bounds__(256) void xconv_kernel(const float* __restrict__ X)
{
    size_t i = ((size_t)blockIdx.x * 256 + threadIdx.x) * 4;
    float4 v = *(const float4*)&X[i];
    *(uint2*)&g_x16[i] = make_uint2(pack_h2(v.x, v.y), pack_h2(v.z, v.w));
}

// ============================================================================
// Prep: transpose [512][N] fp32 -> [N][512] single fp16
// ============================================================================
__global__ void wconv_kernel(const float* __restrict__ W,
                             __half* __restrict__ out, int N)
{
    __shared__ float t[32][33];
    int n = blockIdx.x * 32 + threadIdx.x;
    int k = blockIdx.y * 32 + threadIdx.y;
    t[threadIdx.y][threadIdx.x] = W[(size_t)k * N + n];
    __syncthreads();
    int n2 = blockIdx.x * 32 + threadIdx.y;
    int k2 = blockIdx.y * 32 + threadIdx.x;
    out[(size_t)n2 * DIM + k2] = __float2half_rn(t[threadIdx.x][threadIdx.y]);
}

// ============================================================================
// HMMA GEMM fp16 (single-precision-operand, 1-MMA): 256 thr, 8 warps (4x2),
// warp 32x64, BK=32, 2 smem buffers/stage (A, B), 2-stage cp.async.
// mode 0: epilogue emits fp16 q(scaled)/k/v; mode 1: fp32 C.
// ============================================================================
#define BK   32
#define PAD  40
#define GST  10240
#define GSTAGE (2*GST)             /* A, B */

__global__ __launch_bounds__(256, 2) void gemm_hmma_kernel(
    const __half* __restrict__ A,
    const __half* __restrict__ B,
    float* __restrict__ C, const float* __restrict__ temp, int mode)
{
    extern __shared__ char smem[];
    const uint32_t uS = smem_u32(smem);

    const int tx   = threadIdx.x;
    const int lane = tx & 31;
    const int wid  = tx >> 5;
    const int wm   = wid >> 1;
    const int wn   = wid & 1;
    const int row0 = blockIdx.y * 128;
    const int col0 = blockIdx.x * 128;

    const int cr = tx >> 2;
    const int cc = (tx & 3) << 3;
    auto issue = [&](int kc, int s) {
        uint32_t sb = uS + s * GSTAGE;
#pragma unroll
        for (int t = 0; t < 2; t++) {
            int r = cr + t * 64;
            uint32_t so = (uint32_t)(r * PAD + cc) * 2;
            cp16(sb + so,         A + (size_t)(row0 + r) * DIM + kc + cc);
            cp16(sb + GST + so,   B + (size_t)(col0 + r) * DIM + kc + cc);
        }
        cp_commit();
    };

    float acc[2][8][4];
#pragma unroll
    for (int i = 0; i < 2; i++)
#pragma unroll
        for (int j = 0; j < 8; j++)
#pragma unroll
            for (int t = 0; t < 4; t++) acc[i][j][t] = 0.f;

    const int a_row  = lane & 15;
    const int a_half = lane >> 4;
    const int b_row  = (lane & 7) + ((lane >> 4) << 3);
    const int b_half = (lane >> 3) & 1;

    issue(0, 0);
    const int KITER = DIM / BK;        // 16
    for (int kc = 0; kc < KITER; kc++) {
        if (kc + 1 < KITER) { issue((kc + 1) * BK, (kc + 1) & 1); cp_wait<1>(); }
        else                { cp_wait<0>(); }
        __syncthreads();

        const uint32_t sb = uS + (kc & 1) * GSTAGE;
        const uint32_t uA = sb, uB = sb + GST;
#pragma unroll
        for (int kk = 0; kk < 2; kk++) {
            uint32_t af[2][4];
#pragma unroll
            for (int mf = 0; mf < 2; mf++) {
                uint32_t boff = (uint32_t)((wm * 32 + mf * 16 + a_row) * PAD + kk * 16) * 2
                              + a_half * 16;
                ldm_x4(af[mf], uA + boff);
            }
            uint32_t bf[8][2];
#pragma unroll
            for (int nf2 = 0; nf2 < 4; nf2++) {
                uint32_t boff = (uint32_t)((wn * 64 + nf2 * 16 + b_row) * PAD + kk * 16) * 2
                              + b_half * 16;
                uint32_t th[4];
                ldm_x4(th, uB + boff);
                bf[nf2*2][0] = th[0]; bf[nf2*2][1] = th[1];
                bf[nf2*2+1][0] = th[2]; bf[nf2*2+1][1] = th[3];
            }
#pragma unroll
            for (int mf = 0; mf < 2; mf++)
#pragma unroll
                for (int nf = 0; nf < 8; nf++)
                    mma_fp16(acc[mf][nf], af[mf], bf[nf]);
        }
        __syncthreads();
    }

    // q pre-scale: exp(temperature)*log2(e) -> attention works in log2 domain
    const float sc = (mode == 0) ? __expf(*temp) * 1.44269504f : 1.f;
#pragma unroll
    for (int mf = 0; mf < 2; mf++) {
        int m_base = row0 + wm * 32 + mf * 16 + (lane >> 2);
#pragma unroll
        for (int nf = 0; nf < 8; nf++) {
            int c = col0 + wn * 64 + nf * 8 + 2 * (lane & 3);
            float2 v0 = make_float2(acc[mf][nf][0], acc[mf][nf][1]);
            float2 v1 = make_float2(acc[mf][nf][2], acc[mf][nf][3]);
            if (mode == 1) {
                *(float2*)&C[(size_t)m_base * DIM + c]       = v0;
                *(float2*)&C[(size_t)(m_base + 8) * DIM + c] = v1;
            } else {
                int which = c >> 9;
                int inner = c & 511;
                int h     = inner >> 6;
                int d     = inner & 63;
                int b0 = m_base >> 10, n0 = m_base & 1023;
                int m1 = m_base + 8;
                int b1 = m1 >> 10, n1 = m1 & 1023;
                size_t off0 = ((size_t)((b0 * NHEADS + h) * SEQ + n0)) * DHEAD + d;
                size_t off1 = ((size_t)((b1 * NHEADS + h) * SEQ + n1)) * DHEAD + d;
                __half* dst;
                if (which == 0) {
                    v0.x *= sc; v0.y *= sc; v1.x *= sc; v1.y *= sc;
                    dst = g_q16;
                } else if (which == 1) dst = g_k16;
                else                   dst = g_v16;
                *(uint32_t*)&dst[off0] = pack_h2(v0.x, v0.y);
                *(uint32_t*)&dst[off1] = pack_h2(v1.x, v1.y);
            }
        }
    }
}

// ============================================================================
// Flash attention fp16: q-block 128, 4 warps x 32 q-rows, K-tiles 64.
// QK: single-Q x single-K. PV: single-P x single-V. EX2 softmax.
// 2-stage cp.async (K,V). Output: single fp16 ao.
// ============================================================================
#define KST   72
#define ABUF  9216                 /* 64*KST*2 bytes */
#define ASTAGE (2*ABUF)            /* K, V */

__global__ __launch_bounds__(128, 2) void attn_hmma_kernel()
{
    extern __shared__ char smem[];
    const uint32_t uS = smem_u32(smem);

    const int tx   = threadIdx.x;
    const int lane = tx & 31;
    const int wq   = tx >> 5;
    const int bh   = blockIdx.y;
    const int q0   = blockIdx.x * 128;
    const size_t base = (size_t)bh * SEQ * DHEAD;

    // ---- stage Q (128 rows fp16) into the two stage-0 buffers ----
#pragma unroll
    for (int t = 0; t < 8; t++) {
        int id = tx + t * 128;                 // 0..1023
        int r  = id >> 3, c8 = (id & 7) << 3;  // 128 rows x 8 chunks of 8 halves
        uint32_t hb = (r < 64) ? 0u : (uint32_t)ABUF;
        uint32_t so = (uint32_t)((r & 63) * KST + c8) * 2;
        *(uint4*)(smem + hb + so) = *(const uint4*)&g_q16[base + (size_t)(q0 + r) * DHEAD + c8];
    }
    __syncthreads();

    const int a_row  = lane & 15;
    const int a_half = lane >> 4;
    uint32_t qh[2][4][4];
#pragma unroll
    for (int mf = 0; mf < 2; mf++) {
        int gr = wq * 32 + mf * 16 + a_row;
        uint32_t hb = (gr < 64) ? 0u : (uint32_t)ABUF;
#pragma unroll
        for (int ks = 0; ks < 4; ks++) {
            uint32_t boff = (uint32_t)((gr & 63) * KST + ks * 16) * 2 + a_half * 16;
            ldm_x4(qh[mf][ks], uS + hb + boff);
        }
    }
    __syncthreads();

    const int cr = tx >> 1;
    const int cc = (tx & 1) << 5;
    auto issue = [&](int kt, int s) {
        uint32_t sb = uS + s * ASTAGE;
#pragma unroll
        for (int t = 0; t < 4; t++) {
            int c8 = cc + t * 8;
            uint32_t so = (uint32_t)(cr * KST + c8) * 2;
            size_t g = base + (size_t)(kt * 64 + cr) * DHEAD + c8;
            cp16(sb + so,          g_k16 + g);
            cp16(sb + ABUF + so,   g_v16 + g);
        }
        cp_commit();
    };

    float oacc[2][8][4];
#pragma unroll
    for (int mf = 0; mf < 2; mf++)
#pragma unroll
        for (int i = 0; i < 8; i++)
#pragma unroll
            for (int j = 0; j < 4; j++) oacc[mf][i][j] = 0.f;
    float mrow[4] = {-INFINITY, -INFINITY, -INFINITY, -INFINITY};
    float lrow[4] = {0.f, 0.f, 0.f, 0.f};

    const int b_row  = (lane & 7) + ((lane >> 4) << 3);
    const int b_half = (lane >> 3) & 1;
    const int v_mat  = lane >> 3;
    const int v_row  = lane & 7;
    const int ra     = lane >> 2;
    const int c_in   = 2 * (lane & 3);

    issue(0, 0);
    for (int kt = 0; kt < 16; kt++) {
        if (kt + 1 < 16) { issue(kt + 1, (kt + 1) & 1); cp_wait<1>(); }
        else             { cp_wait<0>(); }
        __syncthreads();

        const uint32_t sb = uS + (kt & 1) * ASTAGE;
        const uint32_t uKh = sb, uVh = sb + ABUF;

        // ---- S = Q K^T ----
        float sacc[2][8][4];
#pragma unroll
        for (int mf = 0; mf < 2; mf++)
#pragma unroll
            for (int i = 0; i < 8; i++)
#pragma unroll
                for (int j = 0; j < 4; j++) sacc[mf][i][j] = 0.f;
#pragma unroll
        for (int nf2 = 0; nf2 < 4; nf2++) {
#pragma unroll
            for (int ks = 0; ks < 4; ks++) {
                uint32_t kh[4];
                uint32_t boff = (uint32_t)((nf2 * 16 + b_row) * KST + ks * 16) * 2 + b_half * 16;
                ldm_x4(kh, uKh + boff);
#pragma unroll
                for (int mf = 0; mf < 2; mf++) {
                    mma_fp16(sacc[mf][2*nf2],   qh[mf][ks], kh);
                    mma_fp16(sacc[mf][2*nf2+1], qh[mf][ks], kh + 2);
                }
            }
        }

        // ---- diagonal mask ----
        if ((kt >> 1) == blockIdx.x) {
#pragma unroll
            for (int mf = 0; mf < 2; mf++) {
                int row_a = q0 + wq * 32 + mf * 16 + ra;
                int row_b = row_a + 8;
#pragma unroll
                for (int nf = 0; nf < 8; nf++) {
                    int col = kt * 64 + nf * 8 + c_in;
                    if (col     == row_a) sacc[mf][nf][0] = -INFINITY;
                    if (col + 1 == row_a) sacc[mf][nf][1] = -INFINITY;
                    if (col     == row_b) sacc[mf][nf][2] = -INFINITY;
                    if (col + 1 == row_b) sacc[mf][nf][3] = -INFINITY;
                }
            }
        }

        // ---- online softmax (base-2, MUFU EX2) ----
        float mt[4] = {-INFINITY, -INFINITY, -INFINITY, -INFINITY};
#pragma unroll
        for (int mf = 0; mf < 2; mf++)
#pragma unroll
            for (int nf = 0; nf < 8; nf++) {
                mt[2*mf]   = fmaxf(mt[2*mf],   fmaxf(sacc[mf][nf][0], sacc[mf][nf][1]));
                mt[2*mf+1] = fmaxf(mt[2*mf+1], fmaxf(sacc[mf][nf][2], sacc[mf][nf][3]));
            }
#pragma unroll
        for (int i = 0; i < 4; i++) {
            mt[i] = fmaxf(mt[i], __shfl_xor_sync(0xffffffffu, mt[i], 1));
            mt[i] = fmaxf(mt[i], __shfl_xor_sync(0xffffffffu, mt[i], 2));
        }

        float mn[4], ls[4] = {0.f, 0.f, 0.f, 0.f};
#pragma unroll
        for (int i = 0; i < 4; i++) mn[i] = fmaxf(mrow[i], mt[i]);
#pragma unroll
        for (int mf = 0; mf < 2; mf++)
#pragma unroll
            for (int nf = 0; nf < 8; nf++) {
                float p0 = ex2(sacc[mf][nf][0] - mn[2*mf]);
                float p1 = ex2(sacc[mf][nf][1] - mn[2*mf]);
                float p2 = ex2(sacc[mf][nf][2] - mn[2*mf+1]);
                float p3 = ex2(sacc[mf][nf][3] - mn[2*mf+1]);
                ls[2*mf] += p0 + p1; ls[2*mf+1] += p2 + p3;
                sacc[mf][nf][0] = p0; sacc[mf][nf][1] = p1;
                sacc[mf][nf][2] = p2; sacc[mf][nf][3] = p3;
            }
#pragma unroll
        for (int i = 0; i < 4; i++) {
            if (mn[i] > mrow[i]) {
                float cr_ = ex2(mrow[i] - mn[i]);
                lrow[i] *= cr_;
                int mf = i >> 1, j0 = (i & 1) * 2;
#pragma unroll
                for (int nf = 0; nf < 8; nf++) {
                    oacc[mf][nf][j0]     *= cr_;
                    oacc[mf][nf][j0 + 1] *= cr_;
                }
                mrow[i] = mn[i];
            }
            lrow[i] += ls[i];
        }

        // ---- O += P V ----
#pragma unroll
        for (int kb = 0; kb < 4; kb++) {
            uint32_t pa[2][4];
#pragma unroll
            for (int mf = 0; mf < 2; mf++) {
                pa[mf][0] = pack_h2(sacc[mf][2*kb][0],   sacc[mf][2*kb][1]);
                pa[mf][1] = pack_h2(sacc[mf][2*kb][2],   sacc[mf][2*kb][3]);
                pa[mf][2] = pack_h2(sacc[mf][2*kb+1][0], sacc[mf][2*kb+1][1]);
                pa[mf][3] = pack_h2(sacc[mf][2*kb+1][2], sacc[mf][2*kb+1][3]);
            }
#pragma unroll
            for (int nf2 = 0; nf2 < 4; nf2++) {
                uint32_t boff = (uint32_t)((kb * 16 + (v_mat & 1) * 8 + v_row) * KST
                                           + nf2 * 16 + (v_mat >> 1) * 8) * 2;
                uint32_t vh[4];
                ldm_x4t(vh, uVh + boff);
#pragma unroll
                for (int mf = 0; mf < 2; mf++) {
                    mma_fp16(oacc[mf][2*nf2],   pa[mf], vh);
                    mma_fp16(oacc[mf][2*nf2+1], pa[mf], vh + 2);
                }
            }
        }
        __syncthreads();
    }

    // ---- finalize: single fp16 ao ----
#pragma unroll
    for (int i = 0; i < 4; i++) {
        lrow[i] += __shfl_xor_sync(0xffffffffu, lrow[i], 1);
        lrow[i] += __shfl_xor_sync(0xffffffffu, lrow[i], 2);
    }

    const int b_ = bh >> 3, h = bh & 7;
#pragma unroll
    for (int mf = 0; mf < 2; mf++) {
        int row_a = q0 + wq * 32 + mf * 16 + ra;
        float inv0 = 1.f / lrow[2*mf], inv1 = 1.f / lrow[2*mf+1];
#pragma unroll
        for (int nf = 0; nf < 8; nf++) {
            int col = h * DHEAD + nf * 8 + c_in;
            size_t o0 = (size_t)(b_ * SEQ + row_a) * INNER + col;
            size_t o1 = (size_t)(b_ * SEQ + row_a + 8) * INNER + col;
            *(uint32_t*)&g_ao16[o0] = pack_h2(oacc[mf][nf][0] * inv0, oacc[mf][nf][1] * inv0);
            *(uint32_t*)&g_ao16[o1] = pack_h2(oacc[mf][nf][2] * inv1, oacc[mf][nf][3] * inv1);
        }
    }
}

// ============================================================================
extern "C" void kernel_launch(void* const* d_in, const int* in_sizes, int n_in,
                              void* d_out, int out_size)
{
    const float* x    = nullptr;
    const float* wqkv = nullptr;
    const float* wout = nullptr;
    const float* temp = nullptr;
    for (int i = 0; i < n_in; i++) {
        switch (in_sizes[i]) {
            case 4194304: x    = (const float*)d_in[i]; break;
            case 786432:  wqkv = (const float*)d_in[i]; break;
            case 262144:  wout = (const float*)d_in[i]; break;
            case 1:       temp = (const float*)d_in[i]; break;
            default: break;
        }
    }
    float* out = (float*)d_out;

    static int attr_done = 0;
    if (!attr_done) {
        cudaFuncSetAttribute(gemm_hmma_kernel,
                             cudaFuncAttributeMaxDynamicSharedMemorySize, 2 * GSTAGE);
        cudaFuncSetAttribute(attn_hmma_kernel,
                             cudaFuncAttributeMaxDynamicSharedMemorySize, 2 * ASTAGE);
        attr_done = 1;
    }

    __half *w16q, *w16o, *x16, *ao16;
    cudaGetSymbolAddress((void**)&w16q, g_w16qkv);
    cudaGetSymbolAddress((void**)&w16o, g_w16out);
    cudaGetSymbolAddress((void**)&x16,  g_x16);
    cudaGetSymbolAddress((void**)&ao16, g_ao16);

    xconv_kernel<<<M_TOT * DIM / (256 * 4), 256>>>(x);
    wconv_kernel<<<dim3(48, 16), dim3(32, 32)>>>(wqkv, w16q, 3 * INNER);
    wconv_kernel<<<dim3(16, 16), dim3(32, 32)>>>(wout, w16o, INNER);

    gemm_hmma_kernel<<<dim3(12, 64), 256, 2 * GSTAGE>>>(x16, w16q, nullptr, temp, 0);
    attn_hmma_kernel<<<dim3(8, 64), 128, 2 * ASTAGE>>>();
    gemm_hmma_kernel<<<dim3(4, 64), 256, 2 * GSTAGE>>>(ao16, w16o, out, temp, 1);
    (void)out_size;
}

// round 15
// speedup vs baseline: 2.6506x; 1.0447x over previous
#include <cuda_runtime.h>
#include <cuda_bf16.h>
#include <cuda_fp16.h>
#include <math.h>
#include <stdint.h>

#define NB      8
#define SEQ     1024
#define DIM     512
#define NHEADS  8
#define DHEAD   64
#define INNER   512
#define M_TOT   (NB*SEQ)        /* 8192 */
#define BH      (NB*NHEADS)     /* 64 */

// ---- scratch (allocation-free: __device__ globals), single fp16 ----
__device__ __half g_x16 [(size_t)M_TOT*DIM];
__device__ __half g_ao16[(size_t)M_TOT*INNER];
// attention operands, [bh][n][d]; q has exp(temperature)*log2(e) folded in
__device__ __half g_q16[(size_t)BH*SEQ*DHEAD];
__device__ __half g_k16[(size_t)BH*SEQ*DHEAD];
__device__ __half g_v16[(size_t)BH*SEQ*DHEAD];
// pre-transposed single-fp16 weights: [n][k]
__device__ __half g_w16qkv[(size_t)3*INNER*DIM];
__device__ __half g_w16out[(size_t)DIM*INNER];

// ========================== helpers ===========================
__device__ __forceinline__ uint32_t smem_u32(const void* p) {
    uint32_t a;
    asm("{ .reg .u64 t; cvta.to.shared.u64 t, %1; cvt.u32.u64 %0, t; }" : "=r"(a) : "l"(p));
    return a;
}
__device__ __forceinline__ void ldm_x4(uint32_t* f, uint32_t addr) {
    asm volatile("ldmatrix.sync.aligned.m8n8.x4.shared.b16 {%0,%1,%2,%3}, [%4];"
                 : "=r"(f[0]), "=r"(f[1]), "=r"(f[2]), "=r"(f[3]) : "r"(addr));
}
__device__ __forceinline__ void ldm_x4t(uint32_t* f, uint32_t addr) {
    asm volatile("ldmatrix.sync.aligned.m8n8.x4.trans.shared.b16 {%0,%1,%2,%3}, [%4];"
                 : "=r"(f[0]), "=r"(f[1]), "=r"(f[2]), "=r"(f[3]) : "r"(addr));
}
__device__ __forceinline__ void mma_fp16(float* d, const uint32_t* a, const uint32_t* b) {
    asm("mma.sync.aligned.m16n8k16.row.col.f32.f16.f16.f32 "
        "{%0,%1,%2,%3}, {%4,%5,%6,%7}, {%8,%9}, {%0,%1,%2,%3};"
        : "+f"(d[0]), "+f"(d[1]), "+f"(d[2]), "+f"(d[3])
        : "r"(a[0]), "r"(a[1]), "r"(a[2]), "r"(a[3]), "r"(b[0]), "r"(b[1]));
}
__device__ __forceinline__ uint32_t pack_h2(float x, float y) {
    __half2 h = __floats2half2_rn(x, y);
    return *(uint32_t*)&h;
}
// hardware EX2 (MUFU); ex2(-inf)=0
__device__ __forceinline__ float ex2(float x) {
    float y;
    asm("ex2.approx.f32 %0, %1;" : "=f"(y) : "f"(x));
    return y;
}
__device__ __forceinline__ void cp16(uint32_t sdst, const void* gsrc) {
    asm volatile("cp.async.cg.shared.global [%0], [%1], 16;" :: "r"(sdst), "l"(gsrc));
}
__device__ __forceinline__ void cp_commit() { asm volatile("cp.async.commit_group;"); }
template <int N> __device__ __forceinline__ void cp_wait() {
    asm volatile("cp.async.wait_group %0;" :: "n"(N));
}

// ============================================================================
// Prep: x fp32 -> single fp16
// ============================================================================
__global__ __launch_bounds__(256) void xconv_kernel(const float* __restrict__ X)
{
    size_t i = ((size_t)blockIdx.x * 256 + threadIdx.x) * 4;
    float4 v = *(const float4*)&X[i];
    *(uint2*)&g_x16[i] = make_uint2(pack_h2(v.x, v.y), pack_h2(v.z, v.w));
}

// ============================================================================
// Prep: transpose [512][N] fp32 -> [N][512] single fp16
// ============================================================================
__global__ void wconv_kernel(const float* __restrict__ W,
                             __half* __restrict__ out, int N)
{
    __shared__ float t[32][33];
    int n = blockIdx.x * 32 + threadIdx.x;
    int k = blockIdx.y * 32 + threadIdx.y;
    t[threadIdx.y][threadIdx.x] = W[(size_t)k * N + n];
    __syncthreads();
    int n2 = blockIdx.x * 32 + threadIdx.y;
    int k2 = blockIdx.y * 32 + threadIdx.x;
    out[(size_t)n2 * DIM + k2] = __float2half_rn(t[threadIdx.x][threadIdx.y]);
}

// ============================================================================
// HMMA GEMM fp16, 3-stage cp.async pipeline, ONE __syncthreads per k-iter.
// 256 thr, 8 warps (4x2), warp 32x64, BK=32, 2 smem buffers/stage (A, B).
// mode 0: epilogue emits fp16 q(scaled)/k/v; mode 1: fp32 C.
// ============================================================================
#define BK   32
#define PAD  40
#define GST  10240
#define GSTAGE (2*GST)             /* A, B */

__global__ __launch_bounds__(256, 2) void gemm_hmma_kernel(
    const __half* __restrict__ A,
    const __half* __restrict__ B,
    float* __restrict__ C, const float* __restrict__ temp, int mode)
{
    extern __shared__ char smem[];
    const uint32_t uS = smem_u32(smem);

    const int tx   = threadIdx.x;
    const int lane = tx & 31;
    const int wid  = tx >> 5;
    const int wm   = wid >> 1;
    const int wn   = wid & 1;
    const int row0 = blockIdx.y * 128;
    const int col0 = blockIdx.x * 128;

    const int cr = tx >> 2;
    const int cc = (tx & 3) << 3;
    auto issue = [&](int kc, int s) {
        uint32_t sb = uS + s * GSTAGE;
#pragma unroll
        for (int t = 0; t < 2; t++) {
            int r = cr + t * 64;
            uint32_t so = (uint32_t)(r * PAD + cc) * 2;
            cp16(sb + so,         A + (size_t)(row0 + r) * DIM + kc + cc);
            cp16(sb + GST + so,   B + (size_t)(col0 + r) * DIM + kc + cc);
        }
        cp_commit();
    };

    float acc[2][8][4];
#pragma unroll
    for (int i = 0; i < 2; i++)
#pragma unroll
        for (int j = 0; j < 8; j++)
#pragma unroll
            for (int t = 0; t < 4; t++) acc[i][j][t] = 0.f;

    const int a_row  = lane & 15;
    const int a_half = lane >> 4;
    const int b_row  = (lane & 7) + ((lane >> 4) << 3);
    const int b_half = (lane >> 3) & 1;

    const int KITER = DIM / BK;        // 16
    issue(0, 0);
    issue(BK, 1);
    for (int kc = 0; kc < KITER; kc++) {
        cp_wait<1>();                  // stage kc%3 complete
        __syncthreads();               // all warps past last read of (kc+2)%3
        if (kc + 2 < KITER) issue((kc + 2) * BK, (kc + 2) % 3);

        const uint32_t sb = uS + (kc % 3) * GSTAGE;
        const uint32_t uA = sb, uB = sb + GST;
#pragma unroll
        for (int kk = 0; kk < 2; kk++) {
            uint32_t af[2][4];
#pragma unroll
            for (int mf = 0; mf < 2; mf++) {
                uint32_t boff = (uint32_t)((wm * 32 + mf * 16 + a_row) * PAD + kk * 16) * 2
                              + a_half * 16;
                ldm_x4(af[mf], uA + boff);
            }
            uint32_t bf[8][2];
#pragma unroll
            for (int nf2 = 0; nf2 < 4; nf2++) {
                uint32_t boff = (uint32_t)((wn * 64 + nf2 * 16 + b_row) * PAD + kk * 16) * 2
                              + b_half * 16;
                uint32_t th[4];
                ldm_x4(th, uB + boff);
                bf[nf2*2][0] = th[0]; bf[nf2*2][1] = th[1];
                bf[nf2*2+1][0] = th[2]; bf[nf2*2+1][1] = th[3];
            }
#pragma unroll
            for (int mf = 0; mf < 2; mf++)
#pragma unroll
                for (int nf = 0; nf < 8; nf++)
                    mma_fp16(acc[mf][nf], af[mf], bf[nf]);
        }
    }

    // q pre-scale: exp(temperature)*log2(e) -> attention works in log2 domain
    const float sc = (mode == 0) ? __expf(*temp) * 1.44269504f : 1.f;
#pragma unroll
    for (int mf = 0; mf < 2; mf++) {
        int m_base = row0 + wm * 32 + mf * 16 + (lane >> 2);
#pragma unroll
        for (int nf = 0; nf < 8; nf++) {
            int c = col0 + wn * 64 + nf * 8 + 2 * (lane & 3);
            float2 v0 = make_float2(acc[mf][nf][0], acc[mf][nf][1]);
            float2 v1 = make_float2(acc[mf][nf][2], acc[mf][nf][3]);
            if (mode == 1) {
                *(float2*)&C[(size_t)m_base * DIM + c]       = v0;
                *(float2*)&C[(size_t)(m_base + 8) * DIM + c] = v1;
            } else {
                int which = c >> 9;
                int inner = c & 511;
                int h     = inner >> 6;
                int d     = inner & 63;
                int b0 = m_base >> 10, n0 = m_base & 1023;
                int m1 = m_base + 8;
                int b1 = m1 >> 10, n1 = m1 & 1023;
                size_t off0 = ((size_t)((b0 * NHEADS + h) * SEQ + n0)) * DHEAD + d;
                size_t off1 = ((size_t)((b1 * NHEADS + h) * SEQ + n1)) * DHEAD + d;
                __half* dst;
                if (which == 0) {
                    v0.x *= sc; v0.y *= sc; v1.x *= sc; v1.y *= sc;
                    dst = g_q16;
                } else if (which == 1) dst = g_k16;
                else                   dst = g_v16;
                *(uint32_t*)&dst[off0] = pack_h2(v0.x, v0.y);
                *(uint32_t*)&dst[off1] = pack_h2(v1.x, v1.y);
            }
        }
    }
}

// ============================================================================
// Flash attention fp16, 3-stage cp.async pipeline, ONE sync per K-tile.
// q-block 128, 4 warps x 32 q-rows, K-tiles 64. EX2 softmax, fp16 ao out.
// ============================================================================
#define KST   72
#define ABUF  9216                 /* 64*KST*2 bytes */
#define ASTAGE (2*ABUF)            /* K, V */

__global__ __launch_bounds__(128, 2) void attn_hmma_kernel()
{
    extern __shared__ char smem[];
    const uint32_t uS = smem_u32(smem);

    const int tx   = threadIdx.x;
    const int lane = tx & 31;
    const int wq   = tx >> 5;
    const int bh   = blockIdx.y;
    const int q0   = blockIdx.x * 128;
    const size_t base = (size_t)bh * SEQ * DHEAD;

    // ---- stage Q (128 rows fp16) into the first two buffers, pull frags ----
#pragma unroll
    for (int t = 0; t < 8; t++) {
        int id = tx + t * 128;                 // 0..1023
        int r  = id >> 3, c8 = (id & 7) << 3;
        uint32_t hb = (r < 64) ? 0u : (uint32_t)ABUF;
        uint32_t so = (uint32_t)((r & 63) * KST + c8) * 2;
        *(uint4*)(smem + hb + so) = *(const uint4*)&g_q16[base + (size_t)(q0 + r) * DHEAD + c8];
    }
    __syncthreads();

    const int a_row  = lane & 15;
    const int a_half = lane >> 4;
    uint32_t qh[2][4][4];
#pragma unroll
    for (int mf = 0; mf < 2; mf++) {
        int gr = wq * 32 + mf * 16 + a_row;
        uint32_t hb = (gr < 64) ? 0u : (uint32_t)ABUF;
#pragma unroll
        for (int ks = 0; ks < 4; ks++) {
            uint32_t boff = (uint32_t)((gr & 63) * KST + ks * 16) * 2 + a_half * 16;
            ldm_x4(qh[mf][ks], uS + hb + boff);
        }
    }
    __syncthreads();

    const int cr = tx >> 1;
    const int cc = (tx & 1) << 5;
    auto issue = [&](int kt, int s) {
        uint32_t sb = uS + s * ASTAGE;
#pragma unroll
        for (int t = 0; t < 4; t++) {
            int c8 = cc + t * 8;
            uint32_t so = (uint32_t)(cr * KST + c8) * 2;
            size_t g = base + (size_t)(kt * 64 + cr) * DHEAD + c8;
            cp16(sb + so,          g_k16 + g);
            cp16(sb + ABUF + so,   g_v16 + g);
        }
        cp_commit();
    };

    float oacc[2][8][4];
#pragma unroll
    for (int mf = 0; mf < 2; mf++)
#pragma unroll
        for (int i = 0; i < 8; i++)
#pragma unroll
            for (int j = 0; j < 4; j++) oacc[mf][i][j] = 0.f;
    float mrow[4] = {-INFINITY, -INFINITY, -INFINITY, -INFINITY};
    float lrow[4] = {0.f, 0.f, 0.f, 0.f};

    const int b_row  = (lane & 7) + ((lane >> 4) << 3);
    const int b_half = (lane >> 3) & 1;
    const int v_mat  = lane >> 3;
    const int v_row  = lane & 7;
    const int ra     = lane >> 2;
    const int c_in   = 2 * (lane & 3);

    issue(0, 0);
    issue(1, 1);
    for (int kt = 0; kt < 16; kt++) {
        cp_wait<1>();                  // stage kt%3 complete
        __syncthreads();               // all warps past last read of (kt+2)%3
        if (kt + 2 < 16) issue(kt + 2, (kt + 2) % 3);

        const uint32_t sb = uS + (kt % 3) * ASTAGE;
        const uint32_t uKh = sb, uVh = sb + ABUF;

        // ---- S = Q K^T ----
        float sacc[2][8][4];
#pragma unroll
        for (int mf = 0; mf < 2; mf++)
#pragma unroll
            for (int i = 0; i < 8; i++)
#pragma unroll
                for (int j = 0; j < 4; j++) sacc[mf][i][j] = 0.f;
#pragma unroll
        for (int nf2 = 0; nf2 < 4; nf2++) {
#pragma unroll
            for (int ks = 0; ks < 4; ks++) {
                uint32_t kh[4];
                uint32_t boff = (uint32_t)((nf2 * 16 + b_row) * KST + ks * 16) * 2 + b_half * 16;
                ldm_x4(kh, uKh + boff);
#pragma unroll
                for (int mf = 0; mf < 2; mf++) {
                    mma_fp16(sacc[mf][2*nf2],   qh[mf][ks], kh);
                    mma_fp16(sacc[mf][2*nf2+1], qh[mf][ks], kh + 2);
                }
            }
        }

        // ---- diagonal mask ----
        if ((kt >> 1) == blockIdx.x) {
#pragma unroll
            for (int mf = 0; mf < 2; mf++) {
                int row_a = q0 + wq * 32 + mf * 16 + ra;
                int row_b = row_a + 8;
#pragma unroll
                for (int nf = 0; nf < 8; nf++) {
                    int col = kt * 64 + nf * 8 + c_in;
                    if (col     == row_a) sacc[mf][nf][0] = -INFINITY;
                    if (col + 1 == row_a) sacc[mf][nf][1] = -INFINITY;
                    if (col     == row_b) sacc[mf][nf][2] = -INFINITY;
                    if (col + 1 == row_b) sacc[mf][nf][3] = -INFINITY;
                }
            }
        }

        // ---- online softmax (base-2, MUFU EX2) ----
        float mt[4] = {-INFINITY, -INFINITY, -INFINITY, -INFINITY};
#pragma unroll
        for (int mf = 0; mf < 2; mf++)
#pragma unroll
            for (int nf = 0; nf < 8; nf++) {
                mt[2*mf]   = fmaxf(mt[2*mf],   fmaxf(sacc[mf][nf][0], sacc[mf][nf][1]));
                mt[2*mf+1] = fmaxf(mt[2*mf+1], fmaxf(sacc[mf][nf][2], sacc[mf][nf][3]));
            }
#pragma unroll
        for (int i = 0; i < 4; i++) {
            mt[i] = fmaxf(mt[i], __shfl_xor_sync(0xffffffffu, mt[i], 1));
            mt[i] = fmaxf(mt[i], __shfl_xor_sync(0xffffffffu, mt[i], 2));
        }

        float mn[4], ls[4] = {0.f, 0.f, 0.f, 0.f};
#pragma unroll
        for (int i = 0; i < 4; i++) mn[i] = fmaxf(mrow[i], mt[i]);
#pragma unroll
        for (int mf = 0; mf < 2; mf++)
#pragma unroll
            for (int nf = 0; nf < 8; nf++) {
                float p0 = ex2(sacc[mf][nf][0] - mn[2*mf]);
                float p1 = ex2(sacc[mf][nf][1] - mn[2*mf]);
                float p2 = ex2(sacc[mf][nf][2] - mn[2*mf+1]);
                float p3 = ex2(sacc[mf][nf][3] - mn[2*mf+1]);
                ls[2*mf] += p0 + p1; ls[2*mf+1] += p2 + p3;
                sacc[mf][nf][0] = p0; sacc[mf][nf][1] = p1;
                sacc[mf][nf][2] = p2; sacc[mf][nf][3] = p3;
            }
#pragma unroll
        for (int i = 0; i < 4; i++) {
            if (mn[i] > mrow[i]) {
                float cr_ = ex2(mrow[i] - mn[i]);
                lrow[i] *= cr_;
                int mf = i >> 1, j0 = (i & 1) * 2;
#pragma unroll
                for (int nf = 0; nf < 8; nf++) {
                    oacc[mf][nf][j0]     *= cr_;
                    oacc[mf][nf][j0 + 1] *= cr_;
                }
                mrow[i] = mn[i];
            }
            lrow[i] += ls[i];
        }

        // ---- O += P V ----
#pragma unroll
        for (int kb = 0; kb < 4; kb++) {
            uint32_t pa[2][4];
#pragma unroll
            for (int mf = 0; mf < 2; mf++) {
                pa[mf][0] = pack_h2(sacc[mf][2*kb][0],   sacc[mf][2*kb][1]);
                pa[mf][1] = pack_h2(sacc[mf][2*kb][2],   sacc[mf][2*kb][3]);
                pa[mf][2] = pack_h2(sacc[mf][2*kb+1][0], sacc[mf][2*kb+1][1]);
                pa[mf][3] = pack_h2(sacc[mf][2*kb+1][2], sacc[mf][2*kb+1][3]);
            }
#pragma unroll
            for (int nf2 = 0; nf2 < 4; nf2++) {
                uint32_t boff = (uint32_t)((kb * 16 + (v_mat & 1) * 8 + v_row) * KST
                                           + nf2 * 16 + (v_mat >> 1) * 8) * 2;
                uint32_t vh[4];
                ldm_x4t(vh, uVh + boff);
#pragma unroll
                for (int mf = 0; mf < 2; mf++) {
                    mma_fp16(oacc[mf][2*nf2],   pa[mf], vh);
                    mma_fp16(oacc[mf][2*nf2+1], pa[mf], vh + 2);
                }
            }
        }
    }

    // ---- finalize: single fp16 ao ----
#pragma unroll
    for (int i = 0; i < 4; i++) {
        lrow[i] += __shfl_xor_sync(0xffffffffu, lrow[i], 1);
        lrow[i] += __shfl_xor_sync(0xffffffffu, lrow[i], 2);
    }

    const int b_ = bh >> 3, h = bh & 7;
#pragma unroll
    for (int mf = 0; mf < 2; mf++) {
        int row_a = q0 + wq * 32 + mf * 16 + ra;
        float inv0 = 1.f / lrow[2*mf], inv1 = 1.f / lrow[2*mf+1];
#pragma unroll
        for (int nf = 0; nf < 8; nf++) {
            int col = h * DHEAD + nf * 8 + c_in;
            size_t o0 = (size_t)(b_ * SEQ + row_a) * INNER + col;
            size_t o1 = (size_t)(b_ * SEQ + row_a + 8) * INNER + col;
            *(uint32_t*)&g_ao16[o0] = pack_h2(oacc[mf][nf][0] * inv0, oacc[mf][nf][1] * inv0);
            *(uint32_t*)&g_ao16[o1] = pack_h2(oacc[mf][nf][2] * inv1, oacc[mf][nf][3] * inv1);
        }
    }
}

// ============================================================================
extern "C" void kernel_launch(void* const* d_in, const int* in_sizes, int n_in,
                              void* d_out, int out_size)
{
    const float* x    = nullptr;
    const float* wqkv = nullptr;
    const float* wout = nullptr;
    const float* temp = nullptr;
    for (int i = 0; i < n_in; i++) {
        switch (in_sizes[i]) {
            case 4194304: x    = (const float*)d_in[i]; break;
            case 786432:  wqkv = (const float*)d_in[i]; break;
            case 262144:  wout = (const float*)d_in[i]; break;
            case 1:       temp = (const float*)d_in[i]; break;
            default: break;
        }
    }
    float* out = (float*)d_out;

    static int attr_done = 0;
    if (!attr_done) {
        cudaFuncSetAttribute(gemm_hmma_kernel,
                             cudaFuncAttributeMaxDynamicSharedMemorySize, 3 * GSTAGE);
        cudaFuncSetAttribute(attn_hmma_kernel,
                             cudaFuncAttributeMaxDynamicSharedMemorySize, 3 * ASTAGE);
        attr_done = 1;
    }

    __half *w16q, *w16o, *x16, *ao16;
    cudaGetSymbolAddress((void**)&w16q, g_w16qkv);
    cudaGetSymbolAddress((void**)&w16o, g_w16out);
    cudaGetSymbolAddress((void**)&x16,  g_x16);
    cudaGetSymbolAddress((void**)&ao16, g_ao16);

    xconv_kernel<<<M_TOT * DIM / (256 * 4), 256>>>(x);
    wconv_kernel<<<dim3(48, 16), dim3(32, 32)>>>(wqkv, w16q, 3 * INNER);
    wconv_kernel<<<dim3(16, 16), dim3(32, 32)>>>(wout, w16o, INNER);

    gemm_hmma_kernel<<<dim3(12, 64), 256, 3 * GSTAGE>>>(x16, w16q, nullptr, temp, 0);
    attn_hmma_kernel<<<dim3(8, 64), 128, 3 * ASTAGE>>>();
    gemm_hmma_kernel<<<dim3(4, 64), 256, 3 * GSTAGE>>>(ao16, w16o, out, temp, 1);
    (void)out_size;
}